// round 1
// baseline (speedup 1.0000x reference)
#include <cuda_runtime.h>
#include <cuda_bf16.h>
#include <math_constants.h>

#define DIM     2048
#define NHEADS  16
#define HD      128
#define BATCH   2
#define SEQ     4096
#define QKV_COLS (3*DIM)   // 6144

// Scratch for Q/K/V in [b][h][n][d] layout (64 MB each) — __device__ globals
// per the allocation rules.
__device__ float g_Q[(size_t)BATCH*NHEADS*SEQ*HD];
__device__ float g_K[(size_t)BATCH*NHEADS*SEQ*HD];
__device__ float g_V[(size_t)BATCH*NHEADS*SEQ*HD];

// ---------------------------------------------------------------------------
// Kernel 1: QKV GEMM  (x[8192,2048] @ W[2048,6144] + b) with de-interleaving
// epilogue: column c -> (h = c/384, d = (c%384)/3, j = c%3) -> g_Q/g_K/g_V.
// Tile 128x128x16, 256 threads, 8x8 per thread.
// ---------------------------------------------------------------------------
__global__ __launch_bounds__(256, 2) void qkv_gemm_kernel(
    const float* __restrict__ x, const float* __restrict__ W,
    const float* __restrict__ bias)
{
    __shared__ float As[16][132];   // A transposed: As[k][m], padded
    __shared__ float Bs[16][132];   // Bs[k][n], padded

    const int tid = threadIdx.x;
    const int tr = tid >> 4;        // 0..15
    const int tc = tid & 15;        // 0..15
    const int gM0 = blockIdx.y << 7;
    const int gN0 = blockIdx.x << 7;

    float acc[8][8];
#pragma unroll
    for (int i = 0; i < 8; i++)
#pragma unroll
        for (int j = 0; j < 8; j++) acc[i][j] = 0.f;

    for (int k0 = 0; k0 < DIM; k0 += 16) {
        // Load A tile 128x16 (transposed into As)
#pragma unroll
        for (int l = 0; l < 2; l++) {
            int f4 = tid + (l << 8);
            int row = f4 >> 2, kc = (f4 & 3) << 2;
            float4 v = *(const float4*)(x + (size_t)(gM0 + row) * DIM + k0 + kc);
            As[kc + 0][row] = v.x;
            As[kc + 1][row] = v.y;
            As[kc + 2][row] = v.z;
            As[kc + 3][row] = v.w;
        }
        // Load B tile 16x128
#pragma unroll
        for (int l = 0; l < 2; l++) {
            int f4 = tid + (l << 8);
            int row = f4 >> 5, cc = (f4 & 31) << 2;
            *(float4*)(&Bs[row][cc]) =
                *(const float4*)(W + (size_t)(k0 + row) * QKV_COLS + gN0 + cc);
        }
        __syncthreads();

#pragma unroll
        for (int kk = 0; kk < 16; kk++) {
            float a[8], bb[8];
            *(float4*)(a)      = *(const float4*)(&As[kk][tr * 8]);
            *(float4*)(a + 4)  = *(const float4*)(&As[kk][tr * 8 + 4]);
            *(float4*)(bb)     = *(const float4*)(&Bs[kk][tc * 8]);
            *(float4*)(bb + 4) = *(const float4*)(&Bs[kk][tc * 8 + 4]);
#pragma unroll
            for (int i = 0; i < 8; i++)
#pragma unroll
                for (int j = 0; j < 8; j++)
                    acc[i][j] = fmaf(a[i], bb[j], acc[i][j]);
        }
        __syncthreads();
    }

    // Epilogue: bias + scatter to Q/K/V scratch
#pragma unroll
    for (int i = 0; i < 8; i++) {
        int r = gM0 + tr * 8 + i;
        int b = r >> 12;            // r / 4096
        int n = r & (SEQ - 1);
#pragma unroll
        for (int j = 0; j < 8; j++) {
            int c = gN0 + tc * 8 + j;
            float v = acc[i][j] + bias[c];
            int h = c / 384;
            int rem = c - h * 384;
            int d = rem / 3;
            int jj = rem - d * 3;
            size_t off = ((size_t)(b * NHEADS + h) * SEQ + n) * HD + d;
            if (jj == 0)      g_Q[off] = v;
            else if (jj == 1) g_K[off] = v;
            else              g_V[off] = v;
        }
    }
}

// ---------------------------------------------------------------------------
// Kernel 2: RMSNorm + rotation-matrix RoPE on Q and K.
// One 128-thread block per (b,h,n) row; pair exchange via shfl_xor(.,1).
// rot flat layout: n*256 + i*4 + r*2 + c  (float4 per (n,i) = [c00,c01,c10,c11])
// ---------------------------------------------------------------------------
__global__ __launch_bounds__(128) void norm_rope_kernel(
    const float* __restrict__ rot, const float* __restrict__ qw,
    const float* __restrict__ kw)
{
    const int row = blockIdx.x;          // (b*H + h)*SEQ + n
    const int n = row & (SEQ - 1);
    const int t = threadIdx.x;           // 0..127

    float qv = g_Q[(size_t)row * HD + t];
    float kv = g_K[(size_t)row * HD + t];
    float q2 = qv * qv, k2 = kv * kv;
#pragma unroll
    for (int off = 16; off; off >>= 1) {
        q2 += __shfl_xor_sync(0xffffffffu, q2, off);
        k2 += __shfl_xor_sync(0xffffffffu, k2, off);
    }
    __shared__ float sq[4], sk[4];
    int w = t >> 5, lane = t & 31;
    if (lane == 0) { sq[w] = q2; sk[w] = k2; }
    __syncthreads();
    q2 = sq[0] + sq[1] + sq[2] + sq[3];
    k2 = sk[0] + sk[1] + sk[2] + sk[3];

    float qs = rsqrtf(q2 * (1.0f / HD) + 1e-6f);
    float ks = rsqrtf(k2 * (1.0f / HD) + 1e-6f);
    float qn = qv * qs * qw[t];
    float kn = kv * ks * kw[t];

    float qp = __shfl_xor_sync(0xffffffffu, qn, 1);
    float kp = __shfl_xor_sync(0xffffffffu, kn, 1);

    int i = t >> 1, r = t & 1;
    float4 rv = *(const float4*)(rot + (size_t)n * 256 + i * 4);
    float c0 = r ? rv.z : rv.x;
    float c1 = r ? rv.w : rv.y;
    float q0 = r ? qp : qn, q1 = r ? qn : qp;
    float k0 = r ? kp : kn, k1 = r ? kn : kp;

    g_Q[(size_t)row * HD + t] = c0 * q0 + c1 * q1;
    g_K[(size_t)row * HD + t] = c0 * k0 + c1 * k1;
}

// ---------------------------------------------------------------------------
// Kernel 3: Flash attention, fp32. BM=BN=64, full D=128 resident in smem.
// 256 threads = 16x16 layout: S microtile 4x4/thread, O microtile 4x8/thread.
// Q/K/V smem rows padded to 33 float4 to avoid 16-way LDS.128 conflicts.
// ---------------------------------------------------------------------------
#define FA_SQ_F4 (64 * 33)
#define FA_SS_ST 65
// floats: 3*2112*4 (Q,K,V as f4) + 64*65 (S) + 3*64 (m,l,alpha)
#define FA_SMEM_BYTES ((3 * FA_SQ_F4 * 4 + 64 * FA_SS_ST + 3 * 64) * 4)

__global__ __launch_bounds__(256) void attn_kernel(float* __restrict__ out)
{
    extern __shared__ float smem[];
    float4* sQ = (float4*)smem;
    float4* sK = sQ + FA_SQ_F4;
    float4* sV = sK + FA_SQ_F4;
    float*  sS = (float*)(sV + FA_SQ_F4);
    float*  sM = sS + 64 * FA_SS_ST;
    float*  sL = sM + 64;
    float*  sA = sL + 64;

    const int bh = blockIdx.y;
    const int q0 = blockIdx.x << 6;
    const int tid = threadIdx.x;
    const int ty = tid >> 4, tx = tid & 15;
    const int r0 = ty * 4;          // 4 S/O rows per thread
    const int c0 = tx * 4;          // 4 S cols per thread
    const int oc0 = tx * 8;         // 8 O cols per thread
    const int wid = tid >> 5, lane = tid & 31;

    // Load Q tile (64 x 128) once
    const float4* Qg = (const float4*)(g_Q + ((size_t)bh * SEQ + q0) * HD);
#pragma unroll
    for (int l = 0; l < 8; l++) {
        int f4 = tid + (l << 8);
        int row = f4 >> 5, col = f4 & 31;
        sQ[row * 33 + col] = Qg[row * 32 + col];
    }
    if (tid < 64) { sM[tid] = -CUDART_INF_F; sL[tid] = 0.f; }

    float o[4][8];
#pragma unroll
    for (int i = 0; i < 4; i++)
#pragma unroll
        for (int j = 0; j < 8; j++) o[i][j] = 0.f;

    const float scale = 0.08838834764831845f;   // 128^-0.5

    for (int kt = 0; kt < SEQ / 64; kt++) {
        __syncthreads();
        const float4* Kg = (const float4*)(g_K + ((size_t)bh * SEQ + kt * 64) * HD);
        const float4* Vg = (const float4*)(g_V + ((size_t)bh * SEQ + kt * 64) * HD);
#pragma unroll
        for (int l = 0; l < 8; l++) {
            int f4 = tid + (l << 8);
            int row = f4 >> 5, col = f4 & 31;
            sK[row * 33 + col] = Kg[row * 32 + col];
            sV[row * 33 + col] = Vg[row * 32 + col];
        }
        __syncthreads();

        // S = Q K^T  (4x4 per thread over d=128)
        float acc[4][4];
#pragma unroll
        for (int i = 0; i < 4; i++)
#pragma unroll
            for (int j = 0; j < 4; j++) acc[i][j] = 0.f;

#pragma unroll 4
        for (int d4 = 0; d4 < 32; d4++) {
            float4 qv[4], kv[4];
#pragma unroll
            for (int i = 0; i < 4; i++) qv[i] = sQ[(r0 + i) * 33 + d4];
#pragma unroll
            for (int j = 0; j < 4; j++) kv[j] = sK[(c0 + j) * 33 + d4];
#pragma unroll
            for (int i = 0; i < 4; i++)
#pragma unroll
                for (int j = 0; j < 4; j++)
                    acc[i][j] += qv[i].x * kv[j].x + qv[i].y * kv[j].y +
                                 qv[i].z * kv[j].z + qv[i].w * kv[j].w;
        }
#pragma unroll
        for (int i = 0; i < 4; i++)
#pragma unroll
            for (int j = 0; j < 4; j++)
                sS[(r0 + i) * FA_SS_ST + c0 + j] = acc[i][j] * scale;
        __syncthreads();

        // Online softmax: warp w handles rows [8w, 8w+8)
#pragma unroll
        for (int rr = 0; rr < 8; rr++) {
            int row = wid * 8 + rr;
            float s0 = sS[row * FA_SS_ST + lane];
            float s1 = sS[row * FA_SS_ST + 32 + lane];
            float mx = fmaxf(s0, s1);
#pragma unroll
            for (int off = 16; off; off >>= 1)
                mx = fmaxf(mx, __shfl_xor_sync(0xffffffffu, mx, off));
            float mold = sM[row];
            float mnew = fmaxf(mold, mx);
            float p0 = __expf(s0 - mnew);
            float p1 = __expf(s1 - mnew);
            float ps = p0 + p1;
#pragma unroll
            for (int off = 16; off; off >>= 1)
                ps += __shfl_xor_sync(0xffffffffu, ps, off);
            if (lane == 0) {
                float al = __expf(mold - mnew);
                sA[row] = al;
                sL[row] = sL[row] * al + ps;
                sM[row] = mnew;
            }
            sS[row * FA_SS_ST + lane] = p0;
            sS[row * FA_SS_ST + 32 + lane] = p1;
        }
        __syncthreads();

        // O = O*alpha + P V  (4x8 per thread over 64 keys)
        float al[4];
#pragma unroll
        for (int i = 0; i < 4; i++) al[i] = sA[r0 + i];
#pragma unroll
        for (int i = 0; i < 4; i++)
#pragma unroll
            for (int j = 0; j < 8; j++) o[i][j] *= al[i];

#pragma unroll 2
        for (int kk = 0; kk < 64; kk++) {
            float p[4];
#pragma unroll
            for (int i = 0; i < 4; i++) p[i] = sS[(r0 + i) * FA_SS_ST + kk];
            float4 v0 = sV[kk * 33 + (oc0 >> 2)];
            float4 v1 = sV[kk * 33 + (oc0 >> 2) + 1];
#pragma unroll
            for (int i = 0; i < 4; i++) {
                o[i][0] = fmaf(p[i], v0.x, o[i][0]);
                o[i][1] = fmaf(p[i], v0.y, o[i][1]);
                o[i][2] = fmaf(p[i], v0.z, o[i][2]);
                o[i][3] = fmaf(p[i], v0.w, o[i][3]);
                o[i][4] = fmaf(p[i], v1.x, o[i][4]);
                o[i][5] = fmaf(p[i], v1.y, o[i][5]);
                o[i][6] = fmaf(p[i], v1.z, o[i][6]);
                o[i][7] = fmaf(p[i], v1.w, o[i][7]);
            }
        }
    }

    // Normalize and write out: out[b, n, h*128 + d]
    const int b = bh >> 4, h = bh & 15;
#pragma unroll
    for (int i = 0; i < 4; i++) {
        int n = q0 + r0 + i;
        float linv = __fdividef(1.0f, sL[r0 + i]);
        float* op = out + ((size_t)b * SEQ + n) * DIM + h * HD + oc0;
        float4 w0 = make_float4(o[i][0] * linv, o[i][1] * linv,
                                o[i][2] * linv, o[i][3] * linv);
        float4 w1 = make_float4(o[i][4] * linv, o[i][5] * linv,
                                o[i][6] * linv, o[i][7] * linv);
        *(float4*)op = w0;
        *(float4*)(op + 4) = w1;
    }
}

// ---------------------------------------------------------------------------
extern "C" void kernel_launch(void* const* d_in, const int* in_sizes, int n_in,
                              void* d_out, int out_size)
{
    const float* x    = (const float*)d_in[0];
    const float* rot  = (const float*)d_in[1];
    const float* W    = (const float*)d_in[2];
    const float* bias = (const float*)d_in[3];
    const float* qw   = (const float*)d_in[4];
    const float* kw   = (const float*)d_in[5];
    float* out = (float*)d_out;

    // 1) QKV projection + de-interleave into g_Q/g_K/g_V
    qkv_gemm_kernel<<<dim3(QKV_COLS / 128, (BATCH * SEQ) / 128), 256>>>(x, W, bias);

    // 2) RMSNorm + RoPE on Q, K
    norm_rope_kernel<<<BATCH * NHEADS * SEQ, 128>>>(rot, qw, kw);

    // 3) Flash attention -> output
    cudaFuncSetAttribute(attn_kernel,
                         cudaFuncAttributeMaxDynamicSharedMemorySize,
                         FA_SMEM_BYTES);
    attn_kernel<<<dim3(SEQ / 64, BATCH * NHEADS), 256, FA_SMEM_BYTES>>>(out);
}

// round 3
// speedup vs baseline: 3.7924x; 3.7924x over previous
#include <cuda_runtime.h>
#include <cuda_bf16.h>
#include <math_constants.h>

#define DIM     2048
#define NHEADS  16
#define HD      128
#define BATCH   2
#define SEQ     4096
#define QKV_COLS (3*DIM)        // 6144
#define MROWS   (BATCH*SEQ)     // 8192

// ---------------------------------------------------------------------------
// Device-global scratch
// ---------------------------------------------------------------------------
__device__ float g_Q[(size_t)BATCH*NHEADS*SEQ*HD];   // pre-norm Q (fp32)
__device__ float g_K[(size_t)BATCH*NHEADS*SEQ*HD];   // pre-norm K (fp32)
__device__ __nv_bfloat16 g_Qh[(size_t)BATCH*NHEADS*SEQ*HD];
__device__ __nv_bfloat16 g_Ql[(size_t)BATCH*NHEADS*SEQ*HD];
__device__ __nv_bfloat16 g_Kh[(size_t)BATCH*NHEADS*SEQ*HD];
__device__ __nv_bfloat16 g_Kl[(size_t)BATCH*NHEADS*SEQ*HD];
__device__ __nv_bfloat16 g_Vh[(size_t)BATCH*NHEADS*SEQ*HD];
__device__ __nv_bfloat16 g_Vl[(size_t)BATCH*NHEADS*SEQ*HD];
__device__ __nv_bfloat16 g_xh[(size_t)MROWS*DIM];
__device__ __nv_bfloat16 g_xl[(size_t)MROWS*DIM];
__device__ __nv_bfloat16 g_wth[(size_t)QKV_COLS*DIM];  // W^T [n][k]
__device__ __nv_bfloat16 g_wtl[(size_t)QKV_COLS*DIM];

// ---------------------------------------------------------------------------
// mma.sync / ldmatrix helpers (arch-neutral PTX, works on compute_103 target)
// ---------------------------------------------------------------------------
__device__ __forceinline__ unsigned smem_u32(const void* p) {
    unsigned a;
    asm("{ .reg .u64 t; cvta.to.shared.u64 t, %1; cvt.u32.u64 %0, t; }"
        : "=r"(a) : "l"(p));
    return a;
}
__device__ __forceinline__ void ldsm_x4(unsigned r[4], unsigned a) {
    asm volatile("ldmatrix.sync.aligned.m8n8.x4.shared.b16 {%0,%1,%2,%3}, [%4];"
                 : "=r"(r[0]), "=r"(r[1]), "=r"(r[2]), "=r"(r[3]) : "r"(a));
}
__device__ __forceinline__ void ldsm_x2(unsigned r[2], unsigned a) {
    asm volatile("ldmatrix.sync.aligned.m8n8.x2.shared.b16 {%0,%1}, [%2];"
                 : "=r"(r[0]), "=r"(r[1]) : "r"(a));
}
__device__ __forceinline__ void ldsm_x2_t(unsigned r[2], unsigned a) {
    asm volatile("ldmatrix.sync.aligned.m8n8.x2.trans.shared.b16 {%0,%1}, [%2];"
                 : "=r"(r[0]), "=r"(r[1]) : "r"(a));
}
__device__ __forceinline__ void mma16816(float c[4], const unsigned a[4],
                                         const unsigned b[2]) {
    asm volatile(
        "mma.sync.aligned.m16n8k16.row.col.f32.bf16.bf16.f32 "
        "{%0,%1,%2,%3}, {%4,%5,%6,%7}, {%8,%9}, {%0,%1,%2,%3};"
        : "+f"(c[0]), "+f"(c[1]), "+f"(c[2]), "+f"(c[3])
        : "r"(a[0]), "r"(a[1]), "r"(a[2]), "r"(a[3]), "r"(b[0]), "r"(b[1]));
}
// pack two floats -> bf16x2 reg, lo in low half
__device__ __forceinline__ unsigned pack_bf16(float lo, float hi) {
    unsigned r;
    asm("cvt.rn.bf16x2.f32 %0, %1, %2;" : "=r"(r) : "f"(hi), "f"(lo));
    return r;
}
__device__ __forceinline__ float bf16_rn(float x) {
    return __bfloat162float(__float2bfloat16(x));
}

// ---------------------------------------------------------------------------
// Kernel 0a: split x (fp32) into bf16 hi/lo
// ---------------------------------------------------------------------------
__global__ void convert_x_kernel(const float* __restrict__ x)
{
    size_t i = ((size_t)blockIdx.x * 256 + threadIdx.x) * 4;
    float4 v = *(const float4*)(x + i);
    float f[4] = {v.x, v.y, v.z, v.w};
    __nv_bfloat16 h[4], lo[4];
#pragma unroll
    for (int j = 0; j < 4; j++) {
        h[j] = __float2bfloat16(f[j]);
        lo[j] = __float2bfloat16(f[j] - __bfloat162float(h[j]));
    }
    *(uint2*)(g_xh + i) = *(uint2*)h;
    *(uint2*)(g_xl + i) = *(uint2*)lo;
}

// ---------------------------------------------------------------------------
// Kernel 0b: transpose W [k][n] -> [n][k], split into bf16 hi/lo
// ---------------------------------------------------------------------------
__global__ void convert_w_kernel(const float* __restrict__ W)
{
    __shared__ float tile[32][33];
    int tx = threadIdx.x, ty = threadIdx.y;          // block (32, 8)
    int n0 = blockIdx.x * 32, k0 = blockIdx.y * 32;
#pragma unroll
    for (int r = 0; r < 4; r++) {
        int k = k0 + ty + r * 8;
        tile[ty + r * 8][tx] = W[(size_t)k * QKV_COLS + n0 + tx];
    }
    __syncthreads();
#pragma unroll
    for (int r = 0; r < 4; r++) {
        int n = n0 + ty + r * 8;
        int k = k0 + tx;
        float v = tile[tx][ty + r * 8];
        __nv_bfloat16 h = __float2bfloat16(v);
        g_wth[(size_t)n * DIM + k] = h;
        g_wtl[(size_t)n * DIM + k] = __float2bfloat16(v - __bfloat162float(h));
    }
}

// ---------------------------------------------------------------------------
// Kernel 1: QKV GEMM via mma.sync bf16 x3 (split precision).
// CTA 128x128, 8 warps (warp_m 0..3 x warp_n 0..1), warp tile 32x64.
// K-chunk 32, double-buffered smem (padded stride 40 bf16 = 80B).
// Epilogue: bias + (h,d,j) de-interleave; Q/K -> fp32, V -> bf16 hi/lo.
// ---------------------------------------------------------------------------
#define G_STR   80                     // smem row stride (bytes)
#define G_ARR   10240                  // one 128x32 bf16 array (w/ pad)
#define G_STAGE (4*G_ARR)              // Ah, Al, Bh, Bl
#define GEMM_SMEM (2*G_STAGE)          // 81920

__global__ __launch_bounds__(256) void qkv_gemm_mma_kernel(
    const float* __restrict__ bias)
{
    extern __shared__ char smem[];
    const unsigned sbase = smem_u32(smem);
    const int tid = threadIdx.x;
    const int wid = tid >> 5, lane = tid & 31;
    const int warp_m = wid >> 1, warp_n = wid & 1;
    const int gM0 = blockIdx.y << 7;
    const int gN0 = blockIdx.x << 7;

    float acc[2][8][4];
#pragma unroll
    for (int i = 0; i < 2; i++)
#pragma unroll
        for (int j = 0; j < 8; j++)
#pragma unroll
            for (int e = 0; e < 4; e++) acc[i][j][e] = 0.f;

    const uint4* src0 = (const uint4*)g_xh;
    const uint4* src1 = (const uint4*)g_xl;
    const uint4* src2 = (const uint4*)g_wth;
    const uint4* src3 = (const uint4*)g_wtl;

    // stage loader: K-chunk at k0 into buffer st (char*)
    auto load_stage = [&](char* st, int k0) {
#pragma unroll
        for (int l = 0; l < 8; l++) {
            int t = tid + (l << 8);
            int arr = t >> 9;            // 0..3
            int w = t & 511;
            int row = w >> 2, c4 = w & 3;
            int grow = (arr < 2 ? gM0 : gN0) + row;
            size_t gi = (((size_t)grow * DIM + k0) >> 3) + c4;
            const uint4* s = (arr == 0) ? src0 : (arr == 1) ? src1
                             : (arr == 2) ? src2 : src3;
            *(uint4*)(st + arr * G_ARR + row * G_STR + c4 * 16) = s[gi];
        }
    };

    load_stage(smem, 0);
    __syncthreads();

    const int l15 = lane & 15;
    const int NIT = DIM / 32;            // 64

    for (int it = 0; it < NIT; ++it) {
        int buf = it & 1;
        if (it + 1 < NIT)
            load_stage(smem + (buf ^ 1) * G_STAGE, (it + 1) * 32);

        unsigned sb = sbase + buf * G_STAGE;
        unsigned sAh = sb, sAl = sb + G_ARR;
        unsigned sBh = sb + 2 * G_ARR, sBl = sb + 3 * G_ARR;

#pragma unroll
        for (int ks = 0; ks < 2; ks++) {
            unsigned ah[2][4], al[2][4];
            int acol = ks * 16 + (lane >> 4) * 8;
#pragma unroll
            for (int i = 0; i < 2; i++) {
                int arow = warp_m * 32 + i * 16 + l15;
                ldsm_x4(ah[i], sAh + arow * G_STR + acol * 2);
                ldsm_x4(al[i], sAl + arow * G_STR + acol * 2);
            }
#pragma unroll
            for (int j = 0; j < 8; j++) {
                unsigned bh[2], bl[2];
                int brow = warp_n * 64 + j * 8 + (lane & 7);
                int bcol = ks * 16 + (l15 >> 3) * 8;
                ldsm_x2(bh, sBh + brow * G_STR + bcol * 2);
                ldsm_x2(bl, sBl + brow * G_STR + bcol * 2);
#pragma unroll
                for (int i = 0; i < 2; i++) {
                    mma16816(acc[i][j], ah[i], bh);
                    mma16816(acc[i][j], ah[i], bl);
                    mma16816(acc[i][j], al[i], bh);
                }
            }
        }
        __syncthreads();
    }

    // Epilogue: direct scatter
    const int gr = lane >> 2, qc = (lane & 3) * 2;
#pragma unroll
    for (int i = 0; i < 2; i++) {
        int rbase = gM0 + warp_m * 32 + i * 16 + gr;
#pragma unroll
        for (int half = 0; half < 2; half++) {
            int row = rbase + half * 8;
            int b = row >> 12;
            int n = row & (SEQ - 1);
#pragma unroll
            for (int j = 0; j < 8; j++) {
                int cb = gN0 + warp_n * 64 + j * 8 + qc;
#pragma unroll
                for (int e = 0; e < 2; e++) {
                    int col = cb + e;
                    float v = acc[i][j][half * 2 + e] + __ldg(bias + col);
                    int h = col / 384;
                    int rem = col - h * 384;
                    int d = rem / 3;
                    int jj = rem - 3 * d;
                    size_t off = ((size_t)(b * NHEADS + h) * SEQ + n) * HD + d;
                    if (jj == 0)      g_Q[off] = v;
                    else if (jj == 1) g_K[off] = v;
                    else {
                        __nv_bfloat16 vh = __float2bfloat16(v);
                        g_Vh[off] = vh;
                        g_Vl[off] = __float2bfloat16(v - __bfloat162float(vh));
                    }
                }
            }
        }
    }
}

// ---------------------------------------------------------------------------
// Kernel 2: RMSNorm + RoPE on Q, K; outputs bf16 hi/lo pairs.
// ---------------------------------------------------------------------------
__global__ __launch_bounds__(128) void norm_rope_kernel(
    const float* __restrict__ rot, const float* __restrict__ qw,
    const float* __restrict__ kw)
{
    const int row = blockIdx.x;          // (b*H + h)*SEQ + n
    const int n = row & (SEQ - 1);
    const int t = threadIdx.x;
    const size_t idx = (size_t)row * HD + t;

    float qv = g_Q[idx];
    float kv = g_K[idx];
    float q2 = qv * qv, k2 = kv * kv;
#pragma unroll
    for (int off = 16; off; off >>= 1) {
        q2 += __shfl_xor_sync(0xffffffffu, q2, off);
        k2 += __shfl_xor_sync(0xffffffffu, k2, off);
    }
    __shared__ float sq[4], sk[4];
    int w = t >> 5, lane = t & 31;
    if (lane == 0) { sq[w] = q2; sk[w] = k2; }
    __syncthreads();
    q2 = sq[0] + sq[1] + sq[2] + sq[3];
    k2 = sk[0] + sk[1] + sk[2] + sk[3];

    float qs = rsqrtf(q2 * (1.0f / HD) + 1e-6f);
    float ks = rsqrtf(k2 * (1.0f / HD) + 1e-6f);
    float qn = qv * qs * qw[t];
    float kn = kv * ks * kw[t];

    float qp = __shfl_xor_sync(0xffffffffu, qn, 1);
    float kp = __shfl_xor_sync(0xffffffffu, kn, 1);

    int i = t >> 1, r = t & 1;
    float4 rv = *(const float4*)(rot + (size_t)n * 256 + i * 4);
    float c0 = r ? rv.z : rv.x;
    float c1 = r ? rv.w : rv.y;
    float q0 = r ? qp : qn, q1 = r ? qn : qp;
    float k0 = r ? kp : kn, k1 = r ? kn : kp;

    float qo = c0 * q0 + c1 * q1;
    float ko = c0 * k0 + c1 * k1;

    __nv_bfloat16 qh = __float2bfloat16(qo);
    __nv_bfloat16 kh = __float2bfloat16(ko);
    g_Qh[idx] = qh;
    g_Ql[idx] = __float2bfloat16(qo - __bfloat162float(qh));
    g_Kh[idx] = kh;
    g_Kl[idx] = __float2bfloat16(ko - __bfloat162float(kh));
}

// ---------------------------------------------------------------------------
// Kernel 3: Flash attention via mma.sync bf16 x3.
// BM=64 (4 warps x m16), BN=64, D=128. Register online softmax.
// smem: Qh,Ql,Kh,Kl,Vh,Vl tiles, 64x128 bf16, padded stride 136.
// ---------------------------------------------------------------------------
#define A_STR   272                     // bytes per smem row (136 bf16)
#define A_ARR   (64*A_STR)              // 17408
#define ATT_SMEM (6*A_ARR)              // 104448

__global__ __launch_bounds__(128) void attn_mma_kernel(float* __restrict__ out)
{
    extern __shared__ char smem[];
    const unsigned sbase = smem_u32(smem);
    const unsigned sQh = sbase, sQl = sbase + A_ARR;
    const unsigned sKh = sbase + 2 * A_ARR, sKl = sbase + 3 * A_ARR;
    const unsigned sVh = sbase + 4 * A_ARR, sVl = sbase + 5 * A_ARR;

    const int bh = blockIdx.y;
    const int q0 = blockIdx.x << 6;
    const int tid = threadIdx.x;
    const int wid = tid >> 5, lane = tid & 31;
    const int l15 = lane & 15;
    const int gr = lane >> 2, qc = (lane & 3) * 2;

    // Load Q tile (once)
    {
        const uint4* Qh4 = (const uint4*)g_Qh;
        const uint4* Ql4 = (const uint4*)g_Ql;
#pragma unroll
        for (int l = 0; l < 8; l++) {
            int t = tid + (l << 7);
            int row = t >> 4, c = t & 15;
            size_t gi = (((size_t)bh * SEQ + q0 + row) * HD >> 3) + c;
            *(uint4*)(smem + row * A_STR + c * 16) = Qh4[gi];
            *(uint4*)(smem + A_ARR + row * A_STR + c * 16) = Ql4[gi];
        }
    }

    float O[16][4];
#pragma unroll
    for (int n = 0; n < 16; n++)
#pragma unroll
        for (int e = 0; e < 4; e++) O[n][e] = 0.f;
    float m0 = -CUDART_INF_F, m1 = -CUDART_INF_F;
    float l0 = 0.f, l1 = 0.f;

    const float scale = 0.08838834764831845f;   // 128^-0.5
    const uint4* Kh4 = (const uint4*)g_Kh;
    const uint4* Kl4 = (const uint4*)g_Kl;
    const uint4* Vh4 = (const uint4*)g_Vh;
    const uint4* Vl4 = (const uint4*)g_Vl;

    for (int kt = 0; kt < SEQ / 64; kt++) {
        __syncthreads();
        // Load K/V tiles (hi/lo)
#pragma unroll
        for (int l = 0; l < 8; l++) {
            int t = tid + (l << 7);
            int row = t >> 4, c = t & 15;
            size_t gi = (((size_t)bh * SEQ + kt * 64 + row) * HD >> 3) + c;
            unsigned boff = row * A_STR + c * 16;
            *(uint4*)(smem + 2 * A_ARR + boff) = Kh4[gi];
            *(uint4*)(smem + 3 * A_ARR + boff) = Kl4[gi];
            *(uint4*)(smem + 4 * A_ARR + boff) = Vh4[gi];
            *(uint4*)(smem + 5 * A_ARR + boff) = Vl4[gi];
        }
        __syncthreads();

        // S = Q K^T (3-term bf16 split), warp owns rows [wid*16, wid*16+16)
        float S[8][4];
#pragma unroll
        for (int j = 0; j < 8; j++)
#pragma unroll
            for (int e = 0; e < 4; e++) S[j][e] = 0.f;

#pragma unroll
        for (int ks = 0; ks < 8; ks++) {
            unsigned qh[4], ql[4];
            int acol = ks * 16 + (lane >> 4) * 8;
            int arow = wid * 16 + l15;
            ldsm_x4(qh, sQh + arow * A_STR + acol * 2);
            ldsm_x4(ql, sQl + arow * A_STR + acol * 2);
#pragma unroll
            for (int j = 0; j < 8; j++) {
                unsigned kh[2], kl[2];
                int brow = j * 8 + (lane & 7);
                int bcol = ks * 16 + (l15 >> 3) * 8;
                ldsm_x2(kh, sKh + brow * A_STR + bcol * 2);
                ldsm_x2(kl, sKl + brow * A_STR + bcol * 2);
                mma16816(S[j], qh, kh);
                mma16816(S[j], qh, kl);
                mma16816(S[j], ql, kh);
            }
        }

        // Online softmax (rows gr and gr+8 of this warp's 16)
        float mx0 = -CUDART_INF_F, mx1 = -CUDART_INF_F;
#pragma unroll
        for (int j = 0; j < 8; j++) {
            S[j][0] *= scale; S[j][1] *= scale;
            S[j][2] *= scale; S[j][3] *= scale;
            mx0 = fmaxf(mx0, fmaxf(S[j][0], S[j][1]));
            mx1 = fmaxf(mx1, fmaxf(S[j][2], S[j][3]));
        }
        mx0 = fmaxf(mx0, __shfl_xor_sync(0xffffffffu, mx0, 1));
        mx0 = fmaxf(mx0, __shfl_xor_sync(0xffffffffu, mx0, 2));
        mx1 = fmaxf(mx1, __shfl_xor_sync(0xffffffffu, mx1, 1));
        mx1 = fmaxf(mx1, __shfl_xor_sync(0xffffffffu, mx1, 2));

        float mn0 = fmaxf(m0, mx0), mn1 = fmaxf(m1, mx1);
        float a0 = __expf(m0 - mn0), a1 = __expf(m1 - mn1);
        m0 = mn0; m1 = mn1;

        float rs0 = 0.f, rs1 = 0.f;
#pragma unroll
        for (int j = 0; j < 8; j++) {
            S[j][0] = __expf(S[j][0] - mn0);
            S[j][1] = __expf(S[j][1] - mn0);
            S[j][2] = __expf(S[j][2] - mn1);
            S[j][3] = __expf(S[j][3] - mn1);
            rs0 += S[j][0] + S[j][1];
            rs1 += S[j][2] + S[j][3];
        }
        rs0 += __shfl_xor_sync(0xffffffffu, rs0, 1);
        rs0 += __shfl_xor_sync(0xffffffffu, rs0, 2);
        rs1 += __shfl_xor_sync(0xffffffffu, rs1, 1);
        rs1 += __shfl_xor_sync(0xffffffffu, rs1, 2);
        l0 = l0 * a0 + rs0;
        l1 = l1 * a1 + rs1;

#pragma unroll
        for (int n = 0; n < 16; n++) {
            O[n][0] *= a0; O[n][1] *= a0;
            O[n][2] *= a1; O[n][3] *= a1;
        }

        // O += P V  (3-term split of P and V)
#pragma unroll
        for (int t = 0; t < 4; t++) {
            unsigned ph[4], pl[4];
            const float* s0 = S[2 * t];
            const float* s1 = S[2 * t + 1];
            ph[0] = pack_bf16(s0[0], s0[1]);
            ph[1] = pack_bf16(s0[2], s0[3]);
            ph[2] = pack_bf16(s1[0], s1[1]);
            ph[3] = pack_bf16(s1[2], s1[3]);
            pl[0] = pack_bf16(s0[0] - bf16_rn(s0[0]), s0[1] - bf16_rn(s0[1]));
            pl[1] = pack_bf16(s0[2] - bf16_rn(s0[2]), s0[3] - bf16_rn(s0[3]));
            pl[2] = pack_bf16(s1[0] - bf16_rn(s1[0]), s1[1] - bf16_rn(s1[1]));
            pl[3] = pack_bf16(s1[2] - bf16_rn(s1[2]), s1[3] - bf16_rn(s1[3]));
#pragma unroll
            for (int n = 0; n < 16; n++) {
                unsigned vh[2], vl[2];
                unsigned vaddr = (t * 16 + l15) * A_STR + n * 16;
                ldsm_x2_t(vh, sVh + vaddr);
                ldsm_x2_t(vl, sVl + vaddr);
                mma16816(O[n], ph, vh);
                mma16816(O[n], ph, vl);
                mma16816(O[n], pl, vh);
            }
        }
    }

    // Write output
    const int b = bh >> 4, h = bh & 15;
    float inv0 = __fdividef(1.0f, l0);
    float inv1 = __fdividef(1.0f, l1);
    int n0g = q0 + wid * 16 + gr;
    float* o0 = out + ((size_t)b * SEQ + n0g) * DIM + h * HD;
    float* o1 = out + ((size_t)b * SEQ + n0g + 8) * DIM + h * HD;
#pragma unroll
    for (int n = 0; n < 16; n++) {
        int d = n * 8 + qc;
        float2 w0 = make_float2(O[n][0] * inv0, O[n][1] * inv0);
        float2 w1 = make_float2(O[n][2] * inv1, O[n][3] * inv1);
        *(float2*)(o0 + d) = w0;
        *(float2*)(o1 + d) = w1;
    }
}

// ---------------------------------------------------------------------------
extern "C" void kernel_launch(void* const* d_in, const int* in_sizes, int n_in,
                              void* d_out, int out_size)
{
    const float* x    = (const float*)d_in[0];
    const float* rot  = (const float*)d_in[1];
    const float* W    = (const float*)d_in[2];
    const float* bias = (const float*)d_in[3];
    const float* qw   = (const float*)d_in[4];
    const float* kw   = (const float*)d_in[5];
    float* out = (float*)d_out;

    convert_x_kernel<<<(MROWS * DIM) / (256 * 4), 256>>>(x);
    convert_w_kernel<<<dim3(QKV_COLS / 32, DIM / 32), dim3(32, 8)>>>(W);

    cudaFuncSetAttribute(qkv_gemm_mma_kernel,
                         cudaFuncAttributeMaxDynamicSharedMemorySize, GEMM_SMEM);
    qkv_gemm_mma_kernel<<<dim3(QKV_COLS / 128, MROWS / 128), 256, GEMM_SMEM>>>(bias);

    norm_rope_kernel<<<BATCH * NHEADS * SEQ, 128>>>(rot, qw, kw);

    cudaFuncSetAttribute(attn_mma_kernel,
                         cudaFuncAttributeMaxDynamicSharedMemorySize, ATT_SMEM);
    attn_mma_kernel<<<dim3(SEQ / 64, BATCH * NHEADS), 128, ATT_SMEM>>>(out);
}

// round 4
// speedup vs baseline: 4.5972x; 1.2122x over previous
#include <cuda_runtime.h>
#include <cuda_bf16.h>
#include <math_constants.h>

#define DIM     2048
#define NHEADS  16
#define HD      128
#define BATCH   2
#define SEQ     4096
#define QKV_COLS (3*DIM)        // 6144
#define MROWS   (BATCH*SEQ)     // 8192

// ---------------------------------------------------------------------------
// Device-global scratch
// ---------------------------------------------------------------------------
__device__ float g_Q[(size_t)BATCH*NHEADS*SEQ*HD];   // pre-norm Q (fp32)
__device__ float g_K[(size_t)BATCH*NHEADS*SEQ*HD];   // pre-norm K (fp32)
__device__ __nv_bfloat16 g_Qh[(size_t)BATCH*NHEADS*SEQ*HD];
__device__ __nv_bfloat16 g_Ql[(size_t)BATCH*NHEADS*SEQ*HD];
__device__ __nv_bfloat16 g_Kh[(size_t)BATCH*NHEADS*SEQ*HD];
__device__ __nv_bfloat16 g_Kl[(size_t)BATCH*NHEADS*SEQ*HD];
__device__ __nv_bfloat16 g_Vh[(size_t)BATCH*NHEADS*SEQ*HD];
__device__ __nv_bfloat16 g_Vl[(size_t)BATCH*NHEADS*SEQ*HD];
__device__ __nv_bfloat16 g_xh[(size_t)MROWS*DIM];
__device__ __nv_bfloat16 g_xl[(size_t)MROWS*DIM];
__device__ __nv_bfloat16 g_wth[(size_t)QKV_COLS*DIM];  // W^T [n][k]
__device__ __nv_bfloat16 g_wtl[(size_t)QKV_COLS*DIM];

// ---------------------------------------------------------------------------
// PTX helpers (arch-neutral: mma.sync / ldmatrix / cp.async, sm_80+)
// ---------------------------------------------------------------------------
__device__ __forceinline__ unsigned smem_u32(const void* p) {
    unsigned a;
    asm("{ .reg .u64 t; cvta.to.shared.u64 t, %1; cvt.u32.u64 %0, t; }"
        : "=r"(a) : "l"(p));
    return a;
}
__device__ __forceinline__ void ldsm_x4(unsigned r[4], unsigned a) {
    asm volatile("ldmatrix.sync.aligned.m8n8.x4.shared.b16 {%0,%1,%2,%3}, [%4];"
                 : "=r"(r[0]), "=r"(r[1]), "=r"(r[2]), "=r"(r[3]) : "r"(a));
}
__device__ __forceinline__ void ldsm_x4_t(unsigned r[4], unsigned a) {
    asm volatile("ldmatrix.sync.aligned.m8n8.x4.trans.shared.b16 {%0,%1,%2,%3}, [%4];"
                 : "=r"(r[0]), "=r"(r[1]), "=r"(r[2]), "=r"(r[3]) : "r"(a));
}
__device__ __forceinline__ void mma16816(float c[4], const unsigned a[4],
                                         const unsigned b[2]) {
    asm volatile(
        "mma.sync.aligned.m16n8k16.row.col.f32.bf16.bf16.f32 "
        "{%0,%1,%2,%3}, {%4,%5,%6,%7}, {%8,%9}, {%0,%1,%2,%3};"
        : "+f"(c[0]), "+f"(c[1]), "+f"(c[2]), "+f"(c[3])
        : "r"(a[0]), "r"(a[1]), "r"(a[2]), "r"(a[3]), "r"(b[0]), "r"(b[1]));
}
__device__ __forceinline__ unsigned pack_bf16(float lo, float hi) {
    unsigned r;
    asm("cvt.rn.bf16x2.f32 %0, %1, %2;" : "=r"(r) : "f"(hi), "f"(lo));
    return r;
}
__device__ __forceinline__ float bf16_rn(float x) {
    return __bfloat162float(__float2bfloat16(x));
}
__device__ __forceinline__ void cp16(unsigned dst, const void* src) {
    asm volatile("cp.async.cg.shared.global [%0], [%1], 16;"
                 :: "r"(dst), "l"(src));
}
#define CP_COMMIT()  asm volatile("cp.async.commit_group;" ::: "memory")
#define CP_WAIT(n)   asm volatile("cp.async.wait_group %0;" :: "n"(n) : "memory")

// ---------------------------------------------------------------------------
// Kernel 0a: split x (fp32) into bf16 hi/lo
// ---------------------------------------------------------------------------
__global__ void convert_x_kernel(const float* __restrict__ x)
{
    size_t i = ((size_t)blockIdx.x * 256 + threadIdx.x) * 4;
    float4 v = *(const float4*)(x + i);
    float f[4] = {v.x, v.y, v.z, v.w};
    __nv_bfloat16 h[4], lo[4];
#pragma unroll
    for (int j = 0; j < 4; j++) {
        h[j] = __float2bfloat16(f[j]);
        lo[j] = __float2bfloat16(f[j] - __bfloat162float(h[j]));
    }
    *(uint2*)(g_xh + i) = *(uint2*)h;
    *(uint2*)(g_xl + i) = *(uint2*)lo;
}

// ---------------------------------------------------------------------------
// Kernel 0b: transpose W [k][n] -> [n][k], split into bf16 hi/lo
// ---------------------------------------------------------------------------
__global__ void convert_w_kernel(const float* __restrict__ W)
{
    __shared__ float tile[32][33];
    int tx = threadIdx.x, ty = threadIdx.y;          // block (32, 8)
    int n0 = blockIdx.x * 32, k0 = blockIdx.y * 32;
#pragma unroll
    for (int r = 0; r < 4; r++) {
        int k = k0 + ty + r * 8;
        tile[ty + r * 8][tx] = W[(size_t)k * QKV_COLS + n0 + tx];
    }
    __syncthreads();
#pragma unroll
    for (int r = 0; r < 4; r++) {
        int n = n0 + ty + r * 8;
        int k = k0 + tx;
        float v = tile[tx][ty + r * 8];
        __nv_bfloat16 h = __float2bfloat16(v);
        g_wth[(size_t)n * DIM + k] = h;
        g_wtl[(size_t)n * DIM + k] = __float2bfloat16(v - __bfloat162float(h));
    }
}

// ---------------------------------------------------------------------------
// Kernel 1: QKV GEMM via mma.sync bf16 x3, CTA 128x256, K-chunk 32,
// 3-stage cp.async pipeline. 8 warps: warp_m(0..3) x warp_n(0..1);
// warp tile 32x128.
// ---------------------------------------------------------------------------
#define G_STR    80                 // smem row stride bytes (32 bf16 + pad)
#define G_A_ARR  (128*G_STR)        // 10240
#define G_B_ARR  (256*G_STR)        // 20480
#define G_STAGE  (2*G_A_ARR + 2*G_B_ARR)   // 61440
#define GEMM_SMEM (3*G_STAGE)       // 184320

__global__ __launch_bounds__(256) void qkv_gemm_mma_kernel(
    const float* __restrict__ bias)
{
    extern __shared__ char smem[];
    const unsigned sbase = smem_u32(smem);
    const int tid = threadIdx.x;
    const int wid = tid >> 5, lane = tid & 31;
    const int warp_m = wid >> 1, warp_n = wid & 1;
    const int gM0 = blockIdx.y << 7;
    const int gN0 = blockIdx.x << 8;
    const int l15 = lane & 15;

    float acc[2][16][4];
#pragma unroll
    for (int i = 0; i < 2; i++)
#pragma unroll
        for (int j = 0; j < 16; j++)
#pragma unroll
            for (int e = 0; e < 4; e++) acc[i][j][e] = 0.f;

    auto stage_load = [&](int st, int it) {
        unsigned sb = sbase + st * G_STAGE;
        int k0 = it * 32;
#pragma unroll
        for (int l = 0; l < 12; l++) {
            int t = tid + (l << 8);                // 0..3071
            if (t < 1024) {                        // A: Ah, Al
                int arr = t >> 9, w = t & 511;
                int row = w >> 2, c4 = w & 3;
                const uint4* s = arr ? (const uint4*)g_xl : (const uint4*)g_xh;
                size_t gi = (((size_t)(gM0 + row) * DIM + k0) >> 3) + c4;
                cp16(sb + arr * G_A_ARR + row * G_STR + c4 * 16, s + gi);
            } else {                               // B: Bh, Bl
                int t2 = t - 1024;
                int arr = t2 >> 10, w = t2 & 1023;
                int row = w >> 2, c4 = w & 3;
                const uint4* s = arr ? (const uint4*)g_wtl : (const uint4*)g_wth;
                size_t gi = (((size_t)(gN0 + row) * DIM + k0) >> 3) + c4;
                cp16(sb + 2 * G_A_ARR + arr * G_B_ARR + row * G_STR + c4 * 16,
                     s + gi);
            }
        }
    };

    const int NIT = DIM / 32;        // 64
    stage_load(0, 0); CP_COMMIT();
    stage_load(1, 1); CP_COMMIT();

    for (int it = 0; it < NIT; ++it) {
        int buf = it % 3;
        if (it + 2 < NIT) stage_load((it + 2) % 3, it + 2);
        CP_COMMIT();
        CP_WAIT(2);
        __syncthreads();

        unsigned sb = sbase + buf * G_STAGE;
        unsigned sAh = sb, sAl = sb + G_A_ARR;
        unsigned sBh = sb + 2 * G_A_ARR, sBl = sb + 2 * G_A_ARR + G_B_ARR;

#pragma unroll
        for (int ks = 0; ks < 2; ks++) {
            unsigned ah[2][4], al[2][4];
            int acol = ks * 16 + (lane >> 4) * 8;
#pragma unroll
            for (int i = 0; i < 2; i++) {
                int arow = warp_m * 32 + i * 16 + l15;
                ldsm_x4(ah[i], sAh + arow * G_STR + acol * 2);
                ldsm_x4(al[i], sAl + arow * G_STR + acol * 2);
            }
            // B fragments in pairs via x4: lanes g=lane>>3 select
            // (j offset, k-half)
            int brow_off = (lane >> 4) * 8 + (lane & 7);
            int bcol = ks * 16 + ((lane >> 3) & 1) * 8;
#pragma unroll
            for (int jj = 0; jj < 8; jj++) {
                unsigned bh4[4], bl4[4];
                unsigned boff = (warp_n * 128 + jj * 16 + brow_off) * G_STR
                                + bcol * 2;
                ldsm_x4(bh4, sBh + boff);
                ldsm_x4(bl4, sBl + boff);
#pragma unroll
                for (int i = 0; i < 2; i++) {
                    mma16816(acc[i][2*jj],   ah[i], bh4);
                    mma16816(acc[i][2*jj],   ah[i], bl4);
                    mma16816(acc[i][2*jj],   al[i], bh4);
                    mma16816(acc[i][2*jj+1], ah[i], bh4 + 2);
                    mma16816(acc[i][2*jj+1], ah[i], bl4 + 2);
                    mma16816(acc[i][2*jj+1], al[i], bh4 + 2);
                }
            }
        }
        __syncthreads();
    }

    // Epilogue: bias + de-interleave scatter
    const int gr = lane >> 2, qc = (lane & 3) * 2;
#pragma unroll
    for (int i = 0; i < 2; i++) {
        int rbase = gM0 + warp_m * 32 + i * 16 + gr;
#pragma unroll
        for (int half = 0; half < 2; half++) {
            int row = rbase + half * 8;
            int b = row >> 12;
            int n = row & (SEQ - 1);
#pragma unroll
            for (int j = 0; j < 16; j++) {
                int cb = gN0 + warp_n * 128 + j * 8 + qc;
#pragma unroll
                for (int e = 0; e < 2; e++) {
                    int col = cb + e;
                    float v = acc[i][j][half * 2 + e] + __ldg(bias + col);
                    int h = col / 384;
                    int rem = col - h * 384;
                    int d = rem / 3;
                    int jj = rem - 3 * d;
                    size_t off = ((size_t)(b * NHEADS + h) * SEQ + n) * HD + d;
                    if (jj == 0)      g_Q[off] = v;
                    else if (jj == 1) g_K[off] = v;
                    else {
                        __nv_bfloat16 vh = __float2bfloat16(v);
                        g_Vh[off] = vh;
                        g_Vl[off] = __float2bfloat16(v - __bfloat162float(vh));
                    }
                }
            }
        }
    }
}

// ---------------------------------------------------------------------------
// Kernel 2: RMSNorm + RoPE on Q, K; outputs bf16 hi/lo pairs.
// ---------------------------------------------------------------------------
__global__ __launch_bounds__(128) void norm_rope_kernel(
    const float* __restrict__ rot, const float* __restrict__ qw,
    const float* __restrict__ kw)
{
    const int row = blockIdx.x;
    const int n = row & (SEQ - 1);
    const int t = threadIdx.x;
    const size_t idx = (size_t)row * HD + t;

    float qv = g_Q[idx];
    float kv = g_K[idx];
    float q2 = qv * qv, k2 = kv * kv;
#pragma unroll
    for (int off = 16; off; off >>= 1) {
        q2 += __shfl_xor_sync(0xffffffffu, q2, off);
        k2 += __shfl_xor_sync(0xffffffffu, k2, off);
    }
    __shared__ float sq[4], sk[4];
    int w = t >> 5, lane = t & 31;
    if (lane == 0) { sq[w] = q2; sk[w] = k2; }
    __syncthreads();
    q2 = sq[0] + sq[1] + sq[2] + sq[3];
    k2 = sk[0] + sk[1] + sk[2] + sk[3];

    float qs = rsqrtf(q2 * (1.0f / HD) + 1e-6f);
    float ks = rsqrtf(k2 * (1.0f / HD) + 1e-6f);
    float qn = qv * qs * qw[t];
    float kn = kv * ks * kw[t];

    float qp = __shfl_xor_sync(0xffffffffu, qn, 1);
    float kp = __shfl_xor_sync(0xffffffffu, kn, 1);

    int i = t >> 1, r = t & 1;
    float4 rv = *(const float4*)(rot + (size_t)n * 256 + i * 4);
    float c0 = r ? rv.z : rv.x;
    float c1 = r ? rv.w : rv.y;
    float q0 = r ? qp : qn, q1 = r ? qn : qp;
    float k0 = r ? kp : kn, k1 = r ? kn : kp;

    float qo = c0 * q0 + c1 * q1;
    float ko = c0 * k0 + c1 * k1;

    __nv_bfloat16 qh = __float2bfloat16(qo);
    __nv_bfloat16 kh = __float2bfloat16(ko);
    g_Qh[idx] = qh;
    g_Ql[idx] = __float2bfloat16(qo - __bfloat162float(qh));
    g_Kh[idx] = kh;
    g_Kl[idx] = __float2bfloat16(ko - __bfloat162float(kh));
}

// ---------------------------------------------------------------------------
// Kernel 3: Flash attention, BM=128 (8 warps x 16 rows), BN=64, D=128.
// Q fragments register-resident; K/V double-buffered via cp.async.
// ---------------------------------------------------------------------------
#define A_STR    272                 // smem row stride bytes (128 bf16 + pad)
#define A_ARR    (64*A_STR)          // 17408 (64-row array)
#define A_STAGE  (4*A_ARR)           // Kh,Kl,Vh,Vl  = 69632
#define ATT_SMEM (2*A_STAGE)         // 139264

__global__ __launch_bounds__(256) void attn_mma_kernel(float* __restrict__ out)
{
    extern __shared__ char smem[];
    const unsigned sbase = smem_u32(smem);
    const int bh = blockIdx.y;
    const int q0 = blockIdx.x << 7;          // 128 rows per CTA
    const int tid = threadIdx.x;
    const int wid = tid >> 5, lane = tid & 31;
    const int l15 = lane & 15;
    const int gr = lane >> 2, qc = (lane & 3) * 2;

    // --- Load Q tile (128 rows, hi/lo) into staging (stage-0 region) ---
    {
        const uint4* Qh4 = (const uint4*)g_Qh;
        const uint4* Ql4 = (const uint4*)g_Ql;
#pragma unroll
        for (int l = 0; l < 16; l++) {
            int t = tid + (l << 8);            // 0..4095
            int arr = t >> 11;                 // 0: hi, 1: lo
            int w = t & 2047;
            int row = w >> 4, c = w & 15;
            size_t gi = (((size_t)bh * SEQ + q0 + row) * HD >> 3) + c;
            const uint4* s = arr ? Ql4 : Qh4;
            cp16(sbase + arr * (128 * A_STR) + row * A_STR + c * 16, s + gi);
        }
    }
    CP_COMMIT();
    CP_WAIT(0);
    __syncthreads();

    // --- Hoist Q fragments to registers (once) ---
    unsigned qfh[8][4], qfl[8][4];
    {
        int arow = wid * 16 + l15;
#pragma unroll
        for (int ks = 0; ks < 8; ks++) {
            int acol = ks * 16 + (lane >> 4) * 8;
            ldsm_x4(qfh[ks], sbase + arow * A_STR + acol * 2);
            ldsm_x4(qfl[ks], sbase + 128 * A_STR + arow * A_STR + acol * 2);
        }
    }
    __syncthreads();   // all warps done reading staging before prefetch

    const uint4* Kh4 = (const uint4*)g_Kh;
    const uint4* Kl4 = (const uint4*)g_Kl;
    const uint4* Vh4 = (const uint4*)g_Vh;
    const uint4* Vl4 = (const uint4*)g_Vl;

    auto stage_load = [&](int st, int kt) {
        unsigned sb = sbase + st * A_STAGE;
#pragma unroll
        for (int l = 0; l < 16; l++) {
            int t = tid + (l << 8);            // 0..4095
            int arr = t >> 10;                 // 0..3: Kh,Kl,Vh,Vl
            int w = t & 1023;
            int row = w >> 4, c = w & 15;
            size_t gi = (((size_t)bh * SEQ + kt * 64 + row) * HD >> 3) + c;
            const uint4* s = (arr == 0) ? Kh4 : (arr == 1) ? Kl4
                             : (arr == 2) ? Vh4 : Vl4;
            cp16(sb + arr * A_ARR + row * A_STR + c * 16, s + gi);
        }
    };

    float O[16][4];
#pragma unroll
    for (int n = 0; n < 16; n++)
#pragma unroll
        for (int e = 0; e < 4; e++) O[n][e] = 0.f;
    float m0 = -CUDART_INF_F, m1 = -CUDART_INF_F;
    float l0 = 0.f, l1 = 0.f;
    const float scale = 0.08838834764831845f;   // 128^-0.5

    const int NKT = SEQ / 64;   // 64
    stage_load(0, 0); CP_COMMIT();

    for (int kt = 0; kt < NKT; kt++) {
        int buf = kt & 1;
        if (kt + 1 < NKT) stage_load(buf ^ 1, kt + 1);
        CP_COMMIT();
        CP_WAIT(1);
        __syncthreads();

        unsigned sb = sbase + buf * A_STAGE;
        unsigned sKh = sb, sKl = sb + A_ARR;
        unsigned sVh = sb + 2 * A_ARR, sVl = sb + 3 * A_ARR;

        // --- S = Q K^T (3-term) ---
        float S[8][4];
#pragma unroll
        for (int j = 0; j < 8; j++)
#pragma unroll
            for (int e = 0; e < 4; e++) S[j][e] = 0.f;

        {
            int brow_off = (lane >> 4) * 8 + (lane & 7);
            int g_kh = ((lane >> 3) & 1) * 8;
#pragma unroll
            for (int ks = 0; ks < 8; ks++) {
                int bcol = ks * 16 + g_kh;
#pragma unroll
                for (int jj = 0; jj < 4; jj++) {
                    unsigned kh4[4], kl4[4];
                    unsigned boff = (jj * 16 + brow_off) * A_STR + bcol * 2;
                    ldsm_x4(kh4, sKh + boff);
                    ldsm_x4(kl4, sKl + boff);
                    mma16816(S[2*jj],   qfh[ks], kh4);
                    mma16816(S[2*jj],   qfh[ks], kl4);
                    mma16816(S[2*jj],   qfl[ks], kh4);
                    mma16816(S[2*jj+1], qfh[ks], kh4 + 2);
                    mma16816(S[2*jj+1], qfh[ks], kl4 + 2);
                    mma16816(S[2*jj+1], qfl[ks], kh4 + 2);
                }
            }
        }

        // --- Online softmax ---
        float mx0 = -CUDART_INF_F, mx1 = -CUDART_INF_F;
#pragma unroll
        for (int j = 0; j < 8; j++) {
            S[j][0] *= scale; S[j][1] *= scale;
            S[j][2] *= scale; S[j][3] *= scale;
            mx0 = fmaxf(mx0, fmaxf(S[j][0], S[j][1]));
            mx1 = fmaxf(mx1, fmaxf(S[j][2], S[j][3]));
        }
        mx0 = fmaxf(mx0, __shfl_xor_sync(0xffffffffu, mx0, 1));
        mx0 = fmaxf(mx0, __shfl_xor_sync(0xffffffffu, mx0, 2));
        mx1 = fmaxf(mx1, __shfl_xor_sync(0xffffffffu, mx1, 1));
        mx1 = fmaxf(mx1, __shfl_xor_sync(0xffffffffu, mx1, 2));

        float mn0 = fmaxf(m0, mx0), mn1 = fmaxf(m1, mx1);
        float a0 = __expf(m0 - mn0), a1 = __expf(m1 - mn1);
        m0 = mn0; m1 = mn1;

        float rs0 = 0.f, rs1 = 0.f;
#pragma unroll
        for (int j = 0; j < 8; j++) {
            S[j][0] = __expf(S[j][0] - mn0);
            S[j][1] = __expf(S[j][1] - mn0);
            S[j][2] = __expf(S[j][2] - mn1);
            S[j][3] = __expf(S[j][3] - mn1);
            rs0 += S[j][0] + S[j][1];
            rs1 += S[j][2] + S[j][3];
        }
        rs0 += __shfl_xor_sync(0xffffffffu, rs0, 1);
        rs0 += __shfl_xor_sync(0xffffffffu, rs0, 2);
        rs1 += __shfl_xor_sync(0xffffffffu, rs1, 1);
        rs1 += __shfl_xor_sync(0xffffffffu, rs1, 2);
        l0 = l0 * a0 + rs0;
        l1 = l1 * a1 + rs1;

#pragma unroll
        for (int n = 0; n < 16; n++) {
            O[n][0] *= a0; O[n][1] *= a0;
            O[n][2] *= a1; O[n][3] *= a1;
        }

        // --- O += P V (3-term) ---
        {
            int vrow_off = (((lane >> 3) & 1) * 8) + (lane & 7);
            int vcol_off = (lane >> 4) * 16;
#pragma unroll
            for (int t = 0; t < 4; t++) {
                unsigned ph[4], pl[4];
                const float* s0 = S[2 * t];
                const float* s1 = S[2 * t + 1];
                ph[0] = pack_bf16(s0[0], s0[1]);
                ph[1] = pack_bf16(s0[2], s0[3]);
                ph[2] = pack_bf16(s1[0], s1[1]);
                ph[3] = pack_bf16(s1[2], s1[3]);
                pl[0] = pack_bf16(s0[0]-bf16_rn(s0[0]), s0[1]-bf16_rn(s0[1]));
                pl[1] = pack_bf16(s0[2]-bf16_rn(s0[2]), s0[3]-bf16_rn(s0[3]));
                pl[2] = pack_bf16(s1[0]-bf16_rn(s1[0]), s1[1]-bf16_rn(s1[1]));
                pl[3] = pack_bf16(s1[2]-bf16_rn(s1[2]), s1[3]-bf16_rn(s1[3]));
#pragma unroll
                for (int nn = 0; nn < 8; nn++) {
                    unsigned vh4[4], vl4[4];
                    unsigned vaddr = (t * 16 + vrow_off) * A_STR
                                     + nn * 32 + vcol_off;
                    ldsm_x4_t(vh4, sVh + vaddr);
                    ldsm_x4_t(vl4, sVl + vaddr);
                    mma16816(O[2*nn],   ph, vh4);
                    mma16816(O[2*nn],   ph, vl4);
                    mma16816(O[2*nn],   pl, vh4);
                    mma16816(O[2*nn+1], ph, vh4 + 2);
                    mma16816(O[2*nn+1], ph, vl4 + 2);
                    mma16816(O[2*nn+1], pl, vh4 + 2);
                }
            }
        }
        __syncthreads();   // all reads of buf done before it is re-filled
    }

    // --- Write output ---
    const int b = bh >> 4, h = bh & 15;
    float inv0 = __fdividef(1.0f, l0);
    float inv1 = __fdividef(1.0f, l1);
    int n0g = q0 + wid * 16 + gr;
    float* o0 = out + ((size_t)b * SEQ + n0g) * DIM + h * HD;
    float* o1 = out + ((size_t)b * SEQ + n0g + 8) * DIM + h * HD;
#pragma unroll
    for (int n = 0; n < 16; n++) {
        int d = n * 8 + qc;
        float2 w0 = make_float2(O[n][0] * inv0, O[n][1] * inv0);
        float2 w1 = make_float2(O[n][2] * inv1, O[n][3] * inv1);
        *(float2*)(o0 + d) = w0;
        *(float2*)(o1 + d) = w1;
    }
}

// ---------------------------------------------------------------------------
extern "C" void kernel_launch(void* const* d_in, const int* in_sizes, int n_in,
                              void* d_out, int out_size)
{
    const float* x    = (const float*)d_in[0];
    const float* rot  = (const float*)d_in[1];
    const float* W    = (const float*)d_in[2];
    const float* bias = (const float*)d_in[3];
    const float* qw   = (const float*)d_in[4];
    const float* kw   = (const float*)d_in[5];
    float* out = (float*)d_out;

    convert_x_kernel<<<(MROWS * DIM) / (256 * 4), 256>>>(x);
    convert_w_kernel<<<dim3(QKV_COLS / 32, DIM / 32), dim3(32, 8)>>>(W);

    cudaFuncSetAttribute(qkv_gemm_mma_kernel,
                         cudaFuncAttributeMaxDynamicSharedMemorySize, GEMM_SMEM);
    qkv_gemm_mma_kernel<<<dim3(QKV_COLS / 256, MROWS / 128), 256, GEMM_SMEM>>>(bias);

    norm_rope_kernel<<<BATCH * NHEADS * SEQ, 128>>>(rot, qw, kw);

    cudaFuncSetAttribute(attn_mma_kernel,
                         cudaFuncAttributeMaxDynamicSharedMemorySize, ATT_SMEM);
    attn_mma_kernel<<<dim3(SEQ / 128, BATCH * NHEADS), 256, ATT_SMEM>>>(out);
}

// round 5
// speedup vs baseline: 4.9187x; 1.0699x over previous
#include <cuda_runtime.h>
#include <cuda_bf16.h>
#include <math_constants.h>

#define DIM     2048
#define NHEADS  16
#define HD      128
#define BATCH   2
#define SEQ     4096
#define QKV_COLS (3*DIM)        // 6144
#define MROWS   (BATCH*SEQ)     // 8192

// ---------------------------------------------------------------------------
// Device-global scratch
// ---------------------------------------------------------------------------
__device__ float g_Q[(size_t)BATCH*NHEADS*SEQ*HD];   // pre-norm Q (fp32)
__device__ float g_K[(size_t)BATCH*NHEADS*SEQ*HD];   // pre-norm K (fp32)
__device__ __nv_bfloat16 g_Qh[(size_t)BATCH*NHEADS*SEQ*HD];
__device__ __nv_bfloat16 g_Ql[(size_t)BATCH*NHEADS*SEQ*HD];
__device__ __nv_bfloat16 g_Kh[(size_t)BATCH*NHEADS*SEQ*HD];
__device__ __nv_bfloat16 g_Kl[(size_t)BATCH*NHEADS*SEQ*HD];
__device__ __nv_bfloat16 g_Vh[(size_t)BATCH*NHEADS*SEQ*HD];
__device__ __nv_bfloat16 g_Vl[(size_t)BATCH*NHEADS*SEQ*HD];
__device__ __nv_bfloat16 g_xh[(size_t)MROWS*DIM];
__device__ __nv_bfloat16 g_xl[(size_t)MROWS*DIM];
__device__ __nv_bfloat16 g_wth[(size_t)QKV_COLS*DIM];  // W^T [n][k]
__device__ __nv_bfloat16 g_wtl[(size_t)QKV_COLS*DIM];

// ---------------------------------------------------------------------------
// PTX helpers (arch-neutral: mma.sync / ldmatrix / cp.async, sm_80+)
// ---------------------------------------------------------------------------
__device__ __forceinline__ unsigned smem_u32(const void* p) {
    unsigned a;
    asm("{ .reg .u64 t; cvta.to.shared.u64 t, %1; cvt.u32.u64 %0, t; }"
        : "=r"(a) : "l"(p));
    return a;
}
__device__ __forceinline__ void ldsm_x4(unsigned r[4], unsigned a) {
    asm volatile("ldmatrix.sync.aligned.m8n8.x4.shared.b16 {%0,%1,%2,%3}, [%4];"
                 : "=r"(r[0]), "=r"(r[1]), "=r"(r[2]), "=r"(r[3]) : "r"(a));
}
__device__ __forceinline__ void ldsm_x4_t(unsigned r[4], unsigned a) {
    asm volatile("ldmatrix.sync.aligned.m8n8.x4.trans.shared.b16 {%0,%1,%2,%3}, [%4];"
                 : "=r"(r[0]), "=r"(r[1]), "=r"(r[2]), "=r"(r[3]) : "r"(a));
}
__device__ __forceinline__ void mma16816(float c[4], const unsigned a[4],
                                         const unsigned b[2]) {
    asm volatile(
        "mma.sync.aligned.m16n8k16.row.col.f32.bf16.bf16.f32 "
        "{%0,%1,%2,%3}, {%4,%5,%6,%7}, {%8,%9}, {%0,%1,%2,%3};"
        : "+f"(c[0]), "+f"(c[1]), "+f"(c[2]), "+f"(c[3])
        : "r"(a[0]), "r"(a[1]), "r"(a[2]), "r"(a[3]), "r"(b[0]), "r"(b[1]));
}
__device__ __forceinline__ unsigned pack_bf16(float lo, float hi) {
    unsigned r;
    asm("cvt.rn.bf16x2.f32 %0, %1, %2;" : "=r"(r) : "f"(hi), "f"(lo));
    return r;
}
__device__ __forceinline__ float bf16_rn(float x) {
    return __bfloat162float(__float2bfloat16(x));
}
__device__ __forceinline__ void cp16(unsigned dst, const void* src) {
    asm volatile("cp.async.cg.shared.global [%0], [%1], 16;"
                 :: "r"(dst), "l"(src));
}
#define CP_COMMIT()  asm volatile("cp.async.commit_group;" ::: "memory")
#define CP_WAIT(n)   asm volatile("cp.async.wait_group %0;" :: "n"(n) : "memory")

// ---------------------------------------------------------------------------
// Kernel 0a: split x (fp32) into bf16 hi/lo
// ---------------------------------------------------------------------------
__global__ void convert_x_kernel(const float* __restrict__ x)
{
    size_t i = ((size_t)blockIdx.x * 256 + threadIdx.x) * 4;
    float4 v = *(const float4*)(x + i);
    float f[4] = {v.x, v.y, v.z, v.w};
    __nv_bfloat16 h[4], lo[4];
#pragma unroll
    for (int j = 0; j < 4; j++) {
        h[j] = __float2bfloat16(f[j]);
        lo[j] = __float2bfloat16(f[j] - __bfloat162float(h[j]));
    }
    *(uint2*)(g_xh + i) = *(uint2*)h;
    *(uint2*)(g_xl + i) = *(uint2*)lo;
}

// ---------------------------------------------------------------------------
// Kernel 0b: transpose W [k][n] -> [n][k], split into bf16 hi/lo
// ---------------------------------------------------------------------------
__global__ void convert_w_kernel(const float* __restrict__ W)
{
    __shared__ float tile[32][33];
    int tx = threadIdx.x, ty = threadIdx.y;          // block (32, 8)
    int n0 = blockIdx.x * 32, k0 = blockIdx.y * 32;
#pragma unroll
    for (int r = 0; r < 4; r++) {
        int k = k0 + ty + r * 8;
        tile[ty + r * 8][tx] = W[(size_t)k * QKV_COLS + n0 + tx];
    }
    __syncthreads();
#pragma unroll
    for (int r = 0; r < 4; r++) {
        int n = n0 + ty + r * 8;
        int k = k0 + tx;
        float v = tile[tx][ty + r * 8];
        __nv_bfloat16 h = __float2bfloat16(v);
        g_wth[(size_t)n * DIM + k] = h;
        g_wtl[(size_t)n * DIM + k] = __float2bfloat16(v - __bfloat162float(h));
    }
}

// ---------------------------------------------------------------------------
// Kernel 1: QKV GEMM via mma.sync bf16 x3, CTA 128x256, K-chunk 64,
// 2-stage cp.async pipeline (221 KB smem). 8 warps, warp tile 32x128.
// ---------------------------------------------------------------------------
#define G_STR    144                // smem row stride bytes (64 bf16 + 16B pad)
#define G_A_ARR  (128*G_STR)        // 18432
#define G_B_ARR  (256*G_STR)        // 36864
#define G_STAGE  (2*G_A_ARR + 2*G_B_ARR)   // 110592
#define GEMM_SMEM (2*G_STAGE)       // 221184

__global__ __launch_bounds__(256, 1) void qkv_gemm_mma_kernel(
    const float* __restrict__ bias)
{
    extern __shared__ char smem[];
    const unsigned sbase = smem_u32(smem);
    const int tid = threadIdx.x;
    const int wid = tid >> 5, lane = tid & 31;
    const int warp_m = wid >> 1, warp_n = wid & 1;
    const int gM0 = blockIdx.y << 7;
    const int gN0 = blockIdx.x << 8;
    const int l15 = lane & 15;

    float acc[2][16][4];
#pragma unroll
    for (int i = 0; i < 2; i++)
#pragma unroll
        for (int j = 0; j < 16; j++)
#pragma unroll
            for (int e = 0; e < 4; e++) acc[i][j][e] = 0.f;

    auto stage_load = [&](int st, int it) {
        unsigned sb = sbase + st * G_STAGE;
        int k0 = it * 64;
#pragma unroll
        for (int l = 0; l < 24; l++) {
            int t = tid + (l << 8);                // 0..6143
            if (t < 2048) {                        // A: Ah, Al
                int arr = t >> 10, w = t & 1023;
                int row = w >> 3, c4 = w & 7;
                const uint4* s = arr ? (const uint4*)g_xl : (const uint4*)g_xh;
                size_t gi = (((size_t)(gM0 + row) * DIM + k0) >> 3) + c4;
                cp16(sb + arr * G_A_ARR + row * G_STR + c4 * 16, s + gi);
            } else {                               // B: Bh, Bl
                int t2 = t - 2048;
                int arr = t2 >> 11, w = t2 & 2047;
                int row = w >> 3, c4 = w & 7;
                const uint4* s = arr ? (const uint4*)g_wtl : (const uint4*)g_wth;
                size_t gi = (((size_t)(gN0 + row) * DIM + k0) >> 3) + c4;
                cp16(sb + 2 * G_A_ARR + arr * G_B_ARR + row * G_STR + c4 * 16,
                     s + gi);
            }
        }
    };

    const int NIT = DIM / 64;        // 32
    stage_load(0, 0); CP_COMMIT();
    stage_load(1, 1); CP_COMMIT();

    for (int it = 0; it < NIT; ++it) {
        CP_WAIT(1);
        __syncthreads();

        unsigned sb = sbase + (it & 1) * G_STAGE;
        unsigned sAh = sb, sAl = sb + G_A_ARR;
        unsigned sBh = sb + 2 * G_A_ARR, sBl = sb + 2 * G_A_ARR + G_B_ARR;

#pragma unroll
        for (int ks = 0; ks < 4; ks++) {
            unsigned ah[2][4], al[2][4];
            int acol = ks * 16 + (lane >> 4) * 8;
#pragma unroll
            for (int i = 0; i < 2; i++) {
                int arow = warp_m * 32 + i * 16 + l15;
                ldsm_x4(ah[i], sAh + arow * G_STR + acol * 2);
                ldsm_x4(al[i], sAl + arow * G_STR + acol * 2);
            }
            int brow_off = (lane >> 4) * 8 + (lane & 7);
            int bcol = ks * 16 + ((lane >> 3) & 1) * 8;
#pragma unroll
            for (int jj = 0; jj < 8; jj++) {
                unsigned bh4[4], bl4[4];
                unsigned boff = (warp_n * 128 + jj * 16 + brow_off) * G_STR
                                + bcol * 2;
                ldsm_x4(bh4, sBh + boff);
                ldsm_x4(bl4, sBl + boff);
#pragma unroll
                for (int i = 0; i < 2; i++) {
                    mma16816(acc[i][2*jj],   ah[i], bh4);
                    mma16816(acc[i][2*jj],   ah[i], bl4);
                    mma16816(acc[i][2*jj],   al[i], bh4);
                    mma16816(acc[i][2*jj+1], ah[i], bh4 + 2);
                    mma16816(acc[i][2*jj+1], ah[i], bl4 + 2);
                    mma16816(acc[i][2*jj+1], al[i], bh4 + 2);
                }
            }
        }
        __syncthreads();                     // all warps done reading stage
        if (it + 2 < NIT) stage_load(it & 1, it + 2);
        CP_COMMIT();                         // unconditional: keeps count in sync
    }

    // Epilogue: bias + de-interleave scatter
    const int gr = lane >> 2, qc = (lane & 3) * 2;
#pragma unroll
    for (int i = 0; i < 2; i++) {
        int rbase = gM0 + warp_m * 32 + i * 16 + gr;
#pragma unroll
        for (int half = 0; half < 2; half++) {
            int row = rbase + half * 8;
            int b = row >> 12;
            int n = row & (SEQ - 1);
#pragma unroll
            for (int j = 0; j < 16; j++) {
                int cb = gN0 + warp_n * 128 + j * 8 + qc;
#pragma unroll
                for (int e = 0; e < 2; e++) {
                    int col = cb + e;
                    float v = acc[i][j][half * 2 + e] + __ldg(bias + col);
                    int h = col / 384;
                    int rem = col - h * 384;
                    int d = rem / 3;
                    int jj = rem - 3 * d;
                    size_t off = ((size_t)(b * NHEADS + h) * SEQ + n) * HD + d;
                    if (jj == 0)      g_Q[off] = v;
                    else if (jj == 1) g_K[off] = v;
                    else {
                        __nv_bfloat16 vh = __float2bfloat16(v);
                        g_Vh[off] = vh;
                        g_Vl[off] = __float2bfloat16(v - __bfloat162float(vh));
                    }
                }
            }
        }
    }
}

// ---------------------------------------------------------------------------
// Kernel 2: RMSNorm + RoPE on Q, K; outputs bf16 hi/lo. Q pre-scaled by
// 1/sqrt(HD) so attention needs no scale multiply.
// ---------------------------------------------------------------------------
__global__ __launch_bounds__(128) void norm_rope_kernel(
    const float* __restrict__ rot, const float* __restrict__ qw,
    const float* __restrict__ kw)
{
    const int row = blockIdx.x;
    const int n = row & (SEQ - 1);
    const int t = threadIdx.x;
    const size_t idx = (size_t)row * HD + t;

    float qv = g_Q[idx];
    float kv = g_K[idx];
    float q2 = qv * qv, k2 = kv * kv;
#pragma unroll
    for (int off = 16; off; off >>= 1) {
        q2 += __shfl_xor_sync(0xffffffffu, q2, off);
        k2 += __shfl_xor_sync(0xffffffffu, k2, off);
    }
    __shared__ float sq[4], sk[4];
    int w = t >> 5, lane = t & 31;
    if (lane == 0) { sq[w] = q2; sk[w] = k2; }
    __syncthreads();
    q2 = sq[0] + sq[1] + sq[2] + sq[3];
    k2 = sk[0] + sk[1] + sk[2] + sk[3];

    float qs = rsqrtf(q2 * (1.0f / HD) + 1e-6f);
    float ks = rsqrtf(k2 * (1.0f / HD) + 1e-6f);
    float qn = qv * qs * qw[t];
    float kn = kv * ks * kw[t];

    float qp = __shfl_xor_sync(0xffffffffu, qn, 1);
    float kp = __shfl_xor_sync(0xffffffffu, kn, 1);

    int i = t >> 1, r = t & 1;
    float4 rv = *(const float4*)(rot + (size_t)n * 256 + i * 4);
    float c0 = r ? rv.z : rv.x;
    float c1 = r ? rv.w : rv.y;
    float q0 = r ? qp : qn, q1 = r ? qn : qp;
    float k0 = r ? kp : kn, k1 = r ? kn : kp;

    const float scale = 0.08838834764831845f;          // 128^-0.5
    float qo = (c0 * q0 + c1 * q1) * scale;            // fold attn scale
    float ko = c0 * k0 + c1 * k1;

    __nv_bfloat16 qh = __float2bfloat16(qo);
    __nv_bfloat16 kh = __float2bfloat16(ko);
    g_Qh[idx] = qh;
    g_Ql[idx] = __float2bfloat16(qo - __bfloat162float(qh));
    g_Kh[idx] = kh;
    g_Kl[idx] = __float2bfloat16(ko - __bfloat162float(kh));
}

// ---------------------------------------------------------------------------
// Kernel 3: Flash attention, BM=128 (8 warps), BN=64, D=128.
// Q fragments register-resident; K/V 3-stage cp.async pipeline,
// ONE barrier per iteration (3rd buffer removes the tail guard sync).
// ---------------------------------------------------------------------------
#define A_STR    272                 // smem row stride bytes (128 bf16 + pad)
#define A_ARR    (64*A_STR)          // 17408 (64-row array)
#define A_STAGE  (4*A_ARR)           // Kh,Kl,Vh,Vl  = 69632
#define ATT_SMEM (3*A_STAGE)         // 208896

__global__ __launch_bounds__(256, 1) void attn_mma_kernel(float* __restrict__ out)
{
    extern __shared__ char smem[];
    const unsigned sbase = smem_u32(smem);
    const int bh = blockIdx.y;
    const int q0 = blockIdx.x << 7;          // 128 rows per CTA
    const int tid = threadIdx.x;
    const int wid = tid >> 5, lane = tid & 31;
    const int l15 = lane & 15;
    const int gr = lane >> 2, qc = (lane & 3) * 2;

    // --- Load Q tile (128 rows, hi/lo) into stage-0 region ---
    {
        const uint4* Qh4 = (const uint4*)g_Qh;
        const uint4* Ql4 = (const uint4*)g_Ql;
#pragma unroll
        for (int l = 0; l < 16; l++) {
            int t = tid + (l << 8);            // 0..4095
            int arr = t >> 11;                 // 0: hi, 1: lo
            int w = t & 2047;
            int row = w >> 4, c = w & 15;
            size_t gi = (((size_t)bh * SEQ + q0 + row) * HD >> 3) + c;
            const uint4* s = arr ? Ql4 : Qh4;
            cp16(sbase + arr * (128 * A_STR) + row * A_STR + c * 16, s + gi);
        }
    }
    CP_COMMIT();
    CP_WAIT(0);
    __syncthreads();

    // --- Hoist Q fragments to registers (once) ---
    unsigned qfh[8][4], qfl[8][4];
    {
        int arow = wid * 16 + l15;
#pragma unroll
        for (int ks = 0; ks < 8; ks++) {
            int acol = ks * 16 + (lane >> 4) * 8;
            ldsm_x4(qfh[ks], sbase + arow * A_STR + acol * 2);
            ldsm_x4(qfl[ks], sbase + 128 * A_STR + arow * A_STR + acol * 2);
        }
    }
    __syncthreads();   // staging free before K/V pipeline reuses it

    const uint4* Kh4 = (const uint4*)g_Kh;
    const uint4* Kl4 = (const uint4*)g_Kl;
    const uint4* Vh4 = (const uint4*)g_Vh;
    const uint4* Vl4 = (const uint4*)g_Vl;

    auto stage_load = [&](int st, int kt) {
        unsigned sb = sbase + st * A_STAGE;
#pragma unroll
        for (int l = 0; l < 16; l++) {
            int t = tid + (l << 8);            // 0..4095
            int arr = t >> 10;                 // 0..3: Kh,Kl,Vh,Vl
            int w = t & 1023;
            int row = w >> 4, c = w & 15;
            size_t gi = (((size_t)bh * SEQ + kt * 64 + row) * HD >> 3) + c;
            const uint4* s = (arr == 0) ? Kh4 : (arr == 1) ? Kl4
                             : (arr == 2) ? Vh4 : Vl4;
            cp16(sb + arr * A_ARR + row * A_STR + c * 16, s + gi);
        }
    };

    float O[16][4];
#pragma unroll
    for (int n = 0; n < 16; n++)
#pragma unroll
        for (int e = 0; e < 4; e++) O[n][e] = 0.f;
    float m0 = -CUDART_INF_F, m1 = -CUDART_INF_F;
    float l0 = 0.f, l1 = 0.f;

    const int NKT = SEQ / 64;   // 64
    stage_load(0, 0); CP_COMMIT();
    stage_load(1, 1); CP_COMMIT();

    int buf = 0;
    for (int kt = 0; kt < NKT; kt++) {
        CP_WAIT(1);
        __syncthreads();        // stage kt visible; all warps done with kt-1

        unsigned sb = sbase + buf * A_STAGE;
        unsigned sKh = sb, sKl = sb + A_ARR;
        unsigned sVh = sb + 2 * A_ARR, sVl = sb + 3 * A_ARR;

        // --- S = Q K^T (3-term) ---
        float S[8][4];
#pragma unroll
        for (int j = 0; j < 8; j++)
#pragma unroll
            for (int e = 0; e < 4; e++) S[j][e] = 0.f;

        {
            int brow_off = (lane >> 4) * 8 + (lane & 7);
            int g_kh = ((lane >> 3) & 1) * 8;
#pragma unroll
            for (int ks = 0; ks < 8; ks++) {
                int bcol = ks * 16 + g_kh;
#pragma unroll
                for (int jj = 0; jj < 4; jj++) {
                    unsigned kh4[4], kl4[4];
                    unsigned boff = (jj * 16 + brow_off) * A_STR + bcol * 2;
                    ldsm_x4(kh4, sKh + boff);
                    ldsm_x4(kl4, sKl + boff);
                    mma16816(S[2*jj],   qfh[ks], kh4);
                    mma16816(S[2*jj],   qfh[ks], kl4);
                    mma16816(S[2*jj],   qfl[ks], kh4);
                    mma16816(S[2*jj+1], qfh[ks], kh4 + 2);
                    mma16816(S[2*jj+1], qfh[ks], kl4 + 2);
                    mma16816(S[2*jj+1], qfl[ks], kh4 + 2);
                }
            }
        }

        // --- Online softmax (scale pre-folded into Q) ---
        float mx0 = -CUDART_INF_F, mx1 = -CUDART_INF_F;
#pragma unroll
        for (int j = 0; j < 8; j++) {
            mx0 = fmaxf(mx0, fmaxf(S[j][0], S[j][1]));
            mx1 = fmaxf(mx1, fmaxf(S[j][2], S[j][3]));
        }
        mx0 = fmaxf(mx0, __shfl_xor_sync(0xffffffffu, mx0, 1));
        mx0 = fmaxf(mx0, __shfl_xor_sync(0xffffffffu, mx0, 2));
        mx1 = fmaxf(mx1, __shfl_xor_sync(0xffffffffu, mx1, 1));
        mx1 = fmaxf(mx1, __shfl_xor_sync(0xffffffffu, mx1, 2));

        float mn0 = fmaxf(m0, mx0), mn1 = fmaxf(m1, mx1);
        float a0 = __expf(m0 - mn0), a1 = __expf(m1 - mn1);
        m0 = mn0; m1 = mn1;

        float rs0 = 0.f, rs1 = 0.f;
#pragma unroll
        for (int j = 0; j < 8; j++) {
            S[j][0] = __expf(S[j][0] - mn0);
            S[j][1] = __expf(S[j][1] - mn0);
            S[j][2] = __expf(S[j][2] - mn1);
            S[j][3] = __expf(S[j][3] - mn1);
            rs0 += S[j][0] + S[j][1];
            rs1 += S[j][2] + S[j][3];
        }
        rs0 += __shfl_xor_sync(0xffffffffu, rs0, 1);
        rs0 += __shfl_xor_sync(0xffffffffu, rs0, 2);
        rs1 += __shfl_xor_sync(0xffffffffu, rs1, 1);
        rs1 += __shfl_xor_sync(0xffffffffu, rs1, 2);
        l0 = l0 * a0 + rs0;
        l1 = l1 * a1 + rs1;

#pragma unroll
        for (int n = 0; n < 16; n++) {
            O[n][0] *= a0; O[n][1] *= a0;
            O[n][2] *= a1; O[n][3] *= a1;
        }

        // --- O += P V (3-term) ---
        {
            int vrow_off = (((lane >> 3) & 1) * 8) + (lane & 7);
            int vcol_off = (lane >> 4) * 16;
#pragma unroll
            for (int t = 0; t < 4; t++) {
                unsigned ph[4], pl[4];
                const float* s0 = S[2 * t];
                const float* s1 = S[2 * t + 1];
                ph[0] = pack_bf16(s0[0], s0[1]);
                ph[1] = pack_bf16(s0[2], s0[3]);
                ph[2] = pack_bf16(s1[0], s1[1]);
                ph[3] = pack_bf16(s1[2], s1[3]);
                pl[0] = pack_bf16(s0[0]-bf16_rn(s0[0]), s0[1]-bf16_rn(s0[1]));
                pl[1] = pack_bf16(s0[2]-bf16_rn(s0[2]), s0[3]-bf16_rn(s0[3]));
                pl[2] = pack_bf16(s1[0]-bf16_rn(s1[0]), s1[1]-bf16_rn(s1[1]));
                pl[3] = pack_bf16(s1[2]-bf16_rn(s1[2]), s1[3]-bf16_rn(s1[3]));
#pragma unroll
                for (int nn = 0; nn < 8; nn++) {
                    unsigned vh4[4], vl4[4];
                    unsigned vaddr = (t * 16 + vrow_off) * A_STR
                                     + nn * 32 + vcol_off;
                    ldsm_x4_t(vh4, sVh + vaddr);
                    ldsm_x4_t(vl4, sVl + vaddr);
                    mma16816(O[2*nn],   ph, vh4);
                    mma16816(O[2*nn],   ph, vl4);
                    mma16816(O[2*nn],   pl, vh4);
                    mma16816(O[2*nn+1], ph, vh4 + 2);
                    mma16816(O[2*nn+1], ph, vl4 + 2);
                    mma16816(O[2*nn+1], pl, vh4 + 2);
                }
            }
        }

        // Prefetch kt+2 into the buffer last used at kt-1 (safe: the barrier
        // at the top of this iteration guarantees every warp left kt-1).
        int nb = buf + 2; if (nb >= 3) nb -= 3;
        if (kt + 2 < NKT) stage_load(nb, kt + 2);
        CP_COMMIT();                         // unconditional, keeps group count
        if (++buf == 3) buf = 0;
    }

    // --- Write output ---
    const int b = bh >> 4, h = bh & 15;
    float inv0 = __fdividef(1.0f, l0);
    float inv1 = __fdividef(1.0f, l1);
    int n0g = q0 + wid * 16 + gr;
    float* o0 = out + ((size_t)b * SEQ + n0g) * DIM + h * HD;
    float* o1 = out + ((size_t)b * SEQ + n0g + 8) * DIM + h * HD;
#pragma unroll
    for (int n = 0; n < 16; n++) {
        int d = n * 8 + qc;
        float2 w0 = make_float2(O[n][0] * inv0, O[n][1] * inv0);
        float2 w1 = make_float2(O[n][2] * inv1, O[n][3] * inv1);
        *(float2*)(o0 + d) = w0;
        *(float2*)(o1 + d) = w1;
    }
}

// ---------------------------------------------------------------------------
extern "C" void kernel_launch(void* const* d_in, const int* in_sizes, int n_in,
                              void* d_out, int out_size)
{
    const float* x    = (const float*)d_in[0];
    const float* rot  = (const float*)d_in[1];
    const float* W    = (const float*)d_in[2];
    const float* bias = (const float*)d_in[3];
    const float* qw   = (const float*)d_in[4];
    const float* kw   = (const float*)d_in[5];
    float* out = (float*)d_out;

    convert_x_kernel<<<(MROWS * DIM) / (256 * 4), 256>>>(x);
    convert_w_kernel<<<dim3(QKV_COLS / 32, DIM / 32), dim3(32, 8)>>>(W);

    cudaFuncSetAttribute(qkv_gemm_mma_kernel,
                         cudaFuncAttributeMaxDynamicSharedMemorySize, GEMM_SMEM);
    qkv_gemm_mma_kernel<<<dim3(QKV_COLS / 256, MROWS / 128), 256, GEMM_SMEM>>>(bias);

    norm_rope_kernel<<<BATCH * NHEADS * SEQ, 128>>>(rot, qw, kw);

    cudaFuncSetAttribute(attn_mma_kernel,
                         cudaFuncAttributeMaxDynamicSharedMemorySize, ATT_SMEM);
    attn_mma_kernel<<<dim3(SEQ / 128, BATCH * NHEADS), 256, ATT_SMEM>>>(out);
}

// round 6
// speedup vs baseline: 5.0952x; 1.0359x over previous
#include <cuda_runtime.h>
#include <cuda_bf16.h>
#include <math_constants.h>

#define DIM     2048
#define NHEADS  16
#define HD      128
#define BATCH   2
#define SEQ     4096
#define QKV_COLS (3*DIM)        // 6144
#define MROWS   (BATCH*SEQ)     // 8192

// ---------------------------------------------------------------------------
// Device-global scratch
// ---------------------------------------------------------------------------
__device__ float g_Q[(size_t)BATCH*NHEADS*SEQ*HD];   // pre-norm Q (fp32)
__device__ float g_K[(size_t)BATCH*NHEADS*SEQ*HD];   // pre-norm K (fp32)
__device__ __nv_bfloat16 g_Qh[(size_t)BATCH*NHEADS*SEQ*HD];
__device__ __nv_bfloat16 g_Ql[(size_t)BATCH*NHEADS*SEQ*HD];
__device__ __nv_bfloat16 g_Kh[(size_t)BATCH*NHEADS*SEQ*HD];
__device__ __nv_bfloat16 g_Kl[(size_t)BATCH*NHEADS*SEQ*HD];
__device__ __nv_bfloat16 g_Vh[(size_t)BATCH*NHEADS*SEQ*HD];
__device__ __nv_bfloat16 g_Vl[(size_t)BATCH*NHEADS*SEQ*HD];
__device__ __nv_bfloat16 g_xh[(size_t)MROWS*DIM];
__device__ __nv_bfloat16 g_xl[(size_t)MROWS*DIM];
__device__ __nv_bfloat16 g_wth[(size_t)QKV_COLS*DIM];  // W^T [n][k]
__device__ __nv_bfloat16 g_wtl[(size_t)QKV_COLS*DIM];

// ---------------------------------------------------------------------------
// PTX helpers (arch-neutral: mma.sync / ldmatrix / cp.async, sm_80+)
// ---------------------------------------------------------------------------
__device__ __forceinline__ unsigned smem_u32(const void* p) {
    unsigned a;
    asm("{ .reg .u64 t; cvta.to.shared.u64 t, %1; cvt.u32.u64 %0, t; }"
        : "=r"(a) : "l"(p));
    return a;
}
__device__ __forceinline__ void ldsm_x4(unsigned r[4], unsigned a) {
    asm volatile("ldmatrix.sync.aligned.m8n8.x4.shared.b16 {%0,%1,%2,%3}, [%4];"
                 : "=r"(r[0]), "=r"(r[1]), "=r"(r[2]), "=r"(r[3]) : "r"(a));
}
__device__ __forceinline__ void ldsm_x4_t(unsigned r[4], unsigned a) {
    asm volatile("ldmatrix.sync.aligned.m8n8.x4.trans.shared.b16 {%0,%1,%2,%3}, [%4];"
                 : "=r"(r[0]), "=r"(r[1]), "=r"(r[2]), "=r"(r[3]) : "r"(a));
}
__device__ __forceinline__ void mma16816(float c[4], const unsigned a[4],
                                         const unsigned b[2]) {
    asm volatile(
        "mma.sync.aligned.m16n8k16.row.col.f32.bf16.bf16.f32 "
        "{%0,%1,%2,%3}, {%4,%5,%6,%7}, {%8,%9}, {%0,%1,%2,%3};"
        : "+f"(c[0]), "+f"(c[1]), "+f"(c[2]), "+f"(c[3])
        : "r"(a[0]), "r"(a[1]), "r"(a[2]), "r"(a[3]), "r"(b[0]), "r"(b[1]));
}
__device__ __forceinline__ unsigned pack_bf16(float lo, float hi) {
    unsigned r;
    asm("cvt.rn.bf16x2.f32 %0, %1, %2;" : "=r"(r) : "f"(hi), "f"(lo));
    return r;
}
__device__ __forceinline__ float bf16_rn(float x) {
    return __bfloat162float(__float2bfloat16(x));
}
__device__ __forceinline__ float ex2(float x) {
    float y;
    asm("ex2.approx.f32 %0, %1;" : "=f"(y) : "f"(x));
    return y;
}
__device__ __forceinline__ void cp16(unsigned dst, const void* src) {
    asm volatile("cp.async.cg.shared.global [%0], [%1], 16;"
                 :: "r"(dst), "l"(src));
}
#define CP_COMMIT()  asm volatile("cp.async.commit_group;" ::: "memory")
#define CP_WAIT(n)   asm volatile("cp.async.wait_group %0;" :: "n"(n) : "memory")

// ---------------------------------------------------------------------------
// Kernel 0a: split x (fp32) into bf16 hi/lo
// ---------------------------------------------------------------------------
__global__ void convert_x_kernel(const float* __restrict__ x)
{
    size_t i = ((size_t)blockIdx.x * 256 + threadIdx.x) * 4;
    float4 v = *(const float4*)(x + i);
    float f[4] = {v.x, v.y, v.z, v.w};
    __nv_bfloat16 h[4], lo[4];
#pragma unroll
    for (int j = 0; j < 4; j++) {
        h[j] = __float2bfloat16(f[j]);
        lo[j] = __float2bfloat16(f[j] - __bfloat162float(h[j]));
    }
    *(uint2*)(g_xh + i) = *(uint2*)h;
    *(uint2*)(g_xl + i) = *(uint2*)lo;
}

// ---------------------------------------------------------------------------
// Kernel 0b: transpose W [k][n] -> [n][k], split into bf16 hi/lo
// ---------------------------------------------------------------------------
__global__ void convert_w_kernel(const float* __restrict__ W)
{
    __shared__ float tile[32][33];
    int tx = threadIdx.x, ty = threadIdx.y;          // block (32, 8)
    int n0 = blockIdx.x * 32, k0 = blockIdx.y * 32;
#pragma unroll
    for (int r = 0; r < 4; r++) {
        int k = k0 + ty + r * 8;
        tile[ty + r * 8][tx] = W[(size_t)k * QKV_COLS + n0 + tx];
    }
    __syncthreads();
#pragma unroll
    for (int r = 0; r < 4; r++) {
        int n = n0 + ty + r * 8;
        int k = k0 + tx;
        float v = tile[tx][ty + r * 8];
        __nv_bfloat16 h = __float2bfloat16(v);
        g_wth[(size_t)n * DIM + k] = h;
        g_wtl[(size_t)n * DIM + k] = __float2bfloat16(v - __bfloat162float(h));
    }
}

// ---------------------------------------------------------------------------
// Kernel 1: QKV GEMM via mma.sync bf16 x3, CTA 128x256, K-chunk 64,
// 2-stage cp.async pipeline (221 KB smem). 8 warps, warp tile 32x128.
// ---------------------------------------------------------------------------
#define G_STR    144                // smem row stride bytes (64 bf16 + 16B pad)
#define G_A_ARR  (128*G_STR)        // 18432
#define G_B_ARR  (256*G_STR)        // 36864
#define G_STAGE  (2*G_A_ARR + 2*G_B_ARR)   // 110592
#define GEMM_SMEM (2*G_STAGE)       // 221184

__global__ __launch_bounds__(256, 1) void qkv_gemm_mma_kernel(
    const float* __restrict__ bias)
{
    extern __shared__ char smem[];
    const unsigned sbase = smem_u32(smem);
    const int tid = threadIdx.x;
    const int wid = tid >> 5, lane = tid & 31;
    const int warp_m = wid >> 1, warp_n = wid & 1;
    const int gM0 = blockIdx.y << 7;
    const int gN0 = blockIdx.x << 8;
    const int l15 = lane & 15;

    float acc[2][16][4];
#pragma unroll
    for (int i = 0; i < 2; i++)
#pragma unroll
        for (int j = 0; j < 16; j++)
#pragma unroll
            for (int e = 0; e < 4; e++) acc[i][j][e] = 0.f;

    auto stage_load = [&](int st, int it) {
        unsigned sb = sbase + st * G_STAGE;
        int k0 = it * 64;
#pragma unroll
        for (int l = 0; l < 24; l++) {
            int t = tid + (l << 8);                // 0..6143
            if (t < 2048) {                        // A: Ah, Al
                int arr = t >> 10, w = t & 1023;
                int row = w >> 3, c4 = w & 7;
                const uint4* s = arr ? (const uint4*)g_xl : (const uint4*)g_xh;
                size_t gi = (((size_t)(gM0 + row) * DIM + k0) >> 3) + c4;
                cp16(sb + arr * G_A_ARR + row * G_STR + c4 * 16, s + gi);
            } else {                               // B: Bh, Bl
                int t2 = t - 2048;
                int arr = t2 >> 11, w = t2 & 2047;
                int row = w >> 3, c4 = w & 7;
                const uint4* s = arr ? (const uint4*)g_wtl : (const uint4*)g_wth;
                size_t gi = (((size_t)(gN0 + row) * DIM + k0) >> 3) + c4;
                cp16(sb + 2 * G_A_ARR + arr * G_B_ARR + row * G_STR + c4 * 16,
                     s + gi);
            }
        }
    };

    const int NIT = DIM / 64;        // 32
    stage_load(0, 0); CP_COMMIT();
    stage_load(1, 1); CP_COMMIT();

    for (int it = 0; it < NIT; ++it) {
        CP_WAIT(1);
        __syncthreads();

        unsigned sb = sbase + (it & 1) * G_STAGE;
        unsigned sAh = sb, sAl = sb + G_A_ARR;
        unsigned sBh = sb + 2 * G_A_ARR, sBl = sb + 2 * G_A_ARR + G_B_ARR;

#pragma unroll
        for (int ks = 0; ks < 4; ks++) {
            unsigned ah[2][4], al[2][4];
            int acol = ks * 16 + (lane >> 4) * 8;
#pragma unroll
            for (int i = 0; i < 2; i++) {
                int arow = warp_m * 32 + i * 16 + l15;
                ldsm_x4(ah[i], sAh + arow * G_STR + acol * 2);
                ldsm_x4(al[i], sAl + arow * G_STR + acol * 2);
            }
            int brow_off = (lane >> 4) * 8 + (lane & 7);
            int bcol = ks * 16 + ((lane >> 3) & 1) * 8;
#pragma unroll
            for (int jj = 0; jj < 8; jj++) {
                unsigned bh4[4], bl4[4];
                unsigned boff = (warp_n * 128 + jj * 16 + brow_off) * G_STR
                                + bcol * 2;
                ldsm_x4(bh4, sBh + boff);
                ldsm_x4(bl4, sBl + boff);
#pragma unroll
                for (int i = 0; i < 2; i++) {
                    mma16816(acc[i][2*jj],   ah[i], bh4);
                    mma16816(acc[i][2*jj],   ah[i], bl4);
                    mma16816(acc[i][2*jj],   al[i], bh4);
                    mma16816(acc[i][2*jj+1], ah[i], bh4 + 2);
                    mma16816(acc[i][2*jj+1], ah[i], bl4 + 2);
                    mma16816(acc[i][2*jj+1], al[i], bh4 + 2);
                }
            }
        }
        __syncthreads();                     // all warps done reading stage
        if (it + 2 < NIT) stage_load(it & 1, it + 2);
        CP_COMMIT();                         // unconditional: keeps count in sync
    }

    // Epilogue: bias + de-interleave scatter
    const int gr = lane >> 2, qc = (lane & 3) * 2;
#pragma unroll
    for (int i = 0; i < 2; i++) {
        int rbase = gM0 + warp_m * 32 + i * 16 + gr;
#pragma unroll
        for (int half = 0; half < 2; half++) {
            int row = rbase + half * 8;
            int b = row >> 12;
            int n = row & (SEQ - 1);
#pragma unroll
            for (int j = 0; j < 16; j++) {
                int cb = gN0 + warp_n * 128 + j * 8 + qc;
#pragma unroll
                for (int e = 0; e < 2; e++) {
                    int col = cb + e;
                    float v = acc[i][j][half * 2 + e] + __ldg(bias + col);
                    int h = col / 384;
                    int rem = col - h * 384;
                    int d = rem / 3;
                    int jj = rem - 3 * d;
                    size_t off = ((size_t)(b * NHEADS + h) * SEQ + n) * HD + d;
                    if (jj == 0)      g_Q[off] = v;
                    else if (jj == 1) g_K[off] = v;
                    else {
                        __nv_bfloat16 vh = __float2bfloat16(v);
                        g_Vh[off] = vh;
                        g_Vl[off] = __float2bfloat16(v - __bfloat162float(vh));
                    }
                }
            }
        }
    }
}

// ---------------------------------------------------------------------------
// Kernel 2: RMSNorm + RoPE on Q, K; outputs bf16 hi/lo. Q pre-scaled by
// (1/sqrt(HD)) * log2(e) so attention scores are directly exp2 arguments.
// ---------------------------------------------------------------------------
__global__ __launch_bounds__(128) void norm_rope_kernel(
    const float* __restrict__ rot, const float* __restrict__ qw,
    const float* __restrict__ kw)
{
    const int row = blockIdx.x;
    const int n = row & (SEQ - 1);
    const int t = threadIdx.x;
    const size_t idx = (size_t)row * HD + t;

    float qv = g_Q[idx];
    float kv = g_K[idx];
    float q2 = qv * qv, k2 = kv * kv;
#pragma unroll
    for (int off = 16; off; off >>= 1) {
        q2 += __shfl_xor_sync(0xffffffffu, q2, off);
        k2 += __shfl_xor_sync(0xffffffffu, k2, off);
    }
    __shared__ float sq[4], sk[4];
    int w = t >> 5, lane = t & 31;
    if (lane == 0) { sq[w] = q2; sk[w] = k2; }
    __syncthreads();
    q2 = sq[0] + sq[1] + sq[2] + sq[3];
    k2 = sk[0] + sk[1] + sk[2] + sk[3];

    float qs = rsqrtf(q2 * (1.0f / HD) + 1e-6f);
    float ks = rsqrtf(k2 * (1.0f / HD) + 1e-6f);
    float qn = qv * qs * qw[t];
    float kn = kv * ks * kw[t];

    float qp = __shfl_xor_sync(0xffffffffu, qn, 1);
    float kp = __shfl_xor_sync(0xffffffffu, kn, 1);

    int i = t >> 1, r = t & 1;
    float4 rv = *(const float4*)(rot + (size_t)n * 256 + i * 4);
    float c0 = r ? rv.z : rv.x;
    float c1 = r ? rv.w : rv.y;
    float q0 = r ? qp : qn, q1 = r ? qn : qp;
    float k0 = r ? kp : kn, k1 = r ? kn : kp;

    // fold attention scale AND log2(e) into Q (scores become exp2 args)
    const float scale = 0.08838834764831845f * 1.4426950408889634f;
    float qo = (c0 * q0 + c1 * q1) * scale;
    float ko = c0 * k0 + c1 * k1;

    __nv_bfloat16 qh = __float2bfloat16(qo);
    __nv_bfloat16 kh = __float2bfloat16(ko);
    g_Qh[idx] = qh;
    g_Ql[idx] = __float2bfloat16(qo - __bfloat162float(qh));
    g_Kh[idx] = kh;
    g_Kl[idx] = __float2bfloat16(ko - __bfloat162float(kh));
}

// ---------------------------------------------------------------------------
// Kernel 3: Flash attention, BM=128 (8 warps), BN=64, D=128.
// Q fragments register-resident; K/V 3-stage cp.async pipeline, 1 barrier/iter.
// NO-MAX softmax: Q,K are RMS-normalized, so |S| <= sqrt(HD)*scale*log2e < 17
// in exp2 domain -> exp2 never overflows fp32. No running max, no O rescale,
// per-thread partial l reduced once at the end.
// ---------------------------------------------------------------------------
#define A_STR    272                 // smem row stride bytes (128 bf16 + pad)
#define A_ARR    (64*A_STR)          // 17408 (64-row array)
#define A_STAGE  (4*A_ARR)           // Kh,Kl,Vh,Vl  = 69632
#define ATT_SMEM (3*A_STAGE)         // 208896

__global__ __launch_bounds__(256, 1) void attn_mma_kernel(float* __restrict__ out)
{
    extern __shared__ char smem[];
    const unsigned sbase = smem_u32(smem);
    const int bh = blockIdx.y;
    const int q0 = blockIdx.x << 7;          // 128 rows per CTA
    const int tid = threadIdx.x;
    const int wid = tid >> 5, lane = tid & 31;
    const int l15 = lane & 15;
    const int gr = lane >> 2, qc = (lane & 3) * 2;

    // --- Load Q tile (128 rows, hi/lo) into stage-0 region ---
    {
        const uint4* Qh4 = (const uint4*)g_Qh;
        const uint4* Ql4 = (const uint4*)g_Ql;
#pragma unroll
        for (int l = 0; l < 16; l++) {
            int t = tid + (l << 8);            // 0..4095
            int arr = t >> 11;                 // 0: hi, 1: lo
            int w = t & 2047;
            int row = w >> 4, c = w & 15;
            size_t gi = (((size_t)bh * SEQ + q0 + row) * HD >> 3) + c;
            const uint4* s = arr ? Ql4 : Qh4;
            cp16(sbase + arr * (128 * A_STR) + row * A_STR + c * 16, s + gi);
        }
    }
    CP_COMMIT();
    CP_WAIT(0);
    __syncthreads();

    // --- Hoist Q fragments to registers (once) ---
    unsigned qfh[8][4], qfl[8][4];
    {
        int arow = wid * 16 + l15;
#pragma unroll
        for (int ks = 0; ks < 8; ks++) {
            int acol = ks * 16 + (lane >> 4) * 8;
            ldsm_x4(qfh[ks], sbase + arow * A_STR + acol * 2);
            ldsm_x4(qfl[ks], sbase + 128 * A_STR + arow * A_STR + acol * 2);
        }
    }
    __syncthreads();   // staging free before K/V pipeline reuses it

    const uint4* Kh4 = (const uint4*)g_Kh;
    const uint4* Kl4 = (const uint4*)g_Kl;
    const uint4* Vh4 = (const uint4*)g_Vh;
    const uint4* Vl4 = (const uint4*)g_Vl;

    auto stage_load = [&](int st, int kt) {
        unsigned sb = sbase + st * A_STAGE;
#pragma unroll
        for (int l = 0; l < 16; l++) {
            int t = tid + (l << 8);            // 0..4095
            int arr = t >> 10;                 // 0..3: Kh,Kl,Vh,Vl
            int w = t & 1023;
            int row = w >> 4, c = w & 15;
            size_t gi = (((size_t)bh * SEQ + kt * 64 + row) * HD >> 3) + c;
            const uint4* s = (arr == 0) ? Kh4 : (arr == 1) ? Kl4
                             : (arr == 2) ? Vh4 : Vl4;
            cp16(sb + arr * A_ARR + row * A_STR + c * 16, s + gi);
        }
    };

    float O[16][4];
#pragma unroll
    for (int n = 0; n < 16; n++)
#pragma unroll
        for (int e = 0; e < 4; e++) O[n][e] = 0.f;
    float l0 = 0.f, l1 = 0.f;              // per-thread partial row sums

    const int NKT = SEQ / 64;   // 64
    stage_load(0, 0); CP_COMMIT();
    stage_load(1, 1); CP_COMMIT();

    int buf = 0;
    for (int kt = 0; kt < NKT; kt++) {
        CP_WAIT(1);
        __syncthreads();        // stage kt visible; all warps done with kt-1

        unsigned sb = sbase + buf * A_STAGE;
        unsigned sKh = sb, sKl = sb + A_ARR;
        unsigned sVh = sb + 2 * A_ARR, sVl = sb + 3 * A_ARR;

        // --- S = Q K^T (3-term), scores already in exp2 domain ---
        float S[8][4];
#pragma unroll
        for (int j = 0; j < 8; j++)
#pragma unroll
            for (int e = 0; e < 4; e++) S[j][e] = 0.f;

        {
            int brow_off = (lane >> 4) * 8 + (lane & 7);
            int g_kh = ((lane >> 3) & 1) * 8;
#pragma unroll
            for (int ks = 0; ks < 8; ks++) {
                int bcol = ks * 16 + g_kh;
#pragma unroll
                for (int jj = 0; jj < 4; jj++) {
                    unsigned kh4[4], kl4[4];
                    unsigned boff = (jj * 16 + brow_off) * A_STR + bcol * 2;
                    ldsm_x4(kh4, sKh + boff);
                    ldsm_x4(kl4, sKl + boff);
                    mma16816(S[2*jj],   qfh[ks], kh4);
                    mma16816(S[2*jj],   qfh[ks], kl4);
                    mma16816(S[2*jj],   qfl[ks], kh4);
                    mma16816(S[2*jj+1], qfh[ks], kh4 + 2);
                    mma16816(S[2*jj+1], qfh[ks], kl4 + 2);
                    mma16816(S[2*jj+1], qfl[ks], kh4 + 2);
                }
            }
        }

        // --- No-max softmax: P = exp2(S); accumulate partial l ---
#pragma unroll
        for (int j = 0; j < 8; j++) {
            S[j][0] = ex2(S[j][0]);
            S[j][1] = ex2(S[j][1]);
            S[j][2] = ex2(S[j][2]);
            S[j][3] = ex2(S[j][3]);
            l0 += S[j][0] + S[j][1];
            l1 += S[j][2] + S[j][3];
        }

        // --- O += P V (3-term) ---
        {
            int vrow_off = (((lane >> 3) & 1) * 8) + (lane & 7);
            int vcol_off = (lane >> 4) * 16;
#pragma unroll
            for (int t = 0; t < 4; t++) {
                unsigned ph[4], pl[4];
                const float* s0 = S[2 * t];
                const float* s1 = S[2 * t + 1];
                ph[0] = pack_bf16(s0[0], s0[1]);
                ph[1] = pack_bf16(s0[2], s0[3]);
                ph[2] = pack_bf16(s1[0], s1[1]);
                ph[3] = pack_bf16(s1[2], s1[3]);
                pl[0] = pack_bf16(s0[0]-bf16_rn(s0[0]), s0[1]-bf16_rn(s0[1]));
                pl[1] = pack_bf16(s0[2]-bf16_rn(s0[2]), s0[3]-bf16_rn(s0[3]));
                pl[2] = pack_bf16(s1[0]-bf16_rn(s1[0]), s1[1]-bf16_rn(s1[1]));
                pl[3] = pack_bf16(s1[2]-bf16_rn(s1[2]), s1[3]-bf16_rn(s1[3]));
#pragma unroll
                for (int nn = 0; nn < 8; nn++) {
                    unsigned vh4[4], vl4[4];
                    unsigned vaddr = (t * 16 + vrow_off) * A_STR
                                     + nn * 32 + vcol_off;
                    ldsm_x4_t(vh4, sVh + vaddr);
                    ldsm_x4_t(vl4, sVl + vaddr);
                    mma16816(O[2*nn],   ph, vh4);
                    mma16816(O[2*nn],   ph, vl4);
                    mma16816(O[2*nn],   pl, vh4);
                    mma16816(O[2*nn+1], ph, vh4 + 2);
                    mma16816(O[2*nn+1], ph, vl4 + 2);
                    mma16816(O[2*nn+1], pl, vh4 + 2);
                }
            }
        }

        // Prefetch kt+2 into the buffer last used at kt-1 (safe: top-of-loop
        // barrier guarantees every warp left kt-1).
        int nb = buf + 2; if (nb >= 3) nb -= 3;
        if (kt + 2 < NKT) stage_load(nb, kt + 2);
        CP_COMMIT();
        if (++buf == 3) buf = 0;
    }

    // --- Final l reduction across the 4 lanes of each row group ---
    l0 += __shfl_xor_sync(0xffffffffu, l0, 1);
    l0 += __shfl_xor_sync(0xffffffffu, l0, 2);
    l1 += __shfl_xor_sync(0xffffffffu, l1, 1);
    l1 += __shfl_xor_sync(0xffffffffu, l1, 2);

    // --- Write output ---
    const int b = bh >> 4, h = bh & 15;
    float inv0 = __fdividef(1.0f, l0);
    float inv1 = __fdividef(1.0f, l1);
    int n0g = q0 + wid * 16 + gr;
    float* o0 = out + ((size_t)b * SEQ + n0g) * DIM + h * HD;
    float* o1 = out + ((size_t)b * SEQ + n0g + 8) * DIM + h * HD;
#pragma unroll
    for (int n = 0; n < 16; n++) {
        int d = n * 8 + qc;
        float2 w0 = make_float2(O[n][0] * inv0, O[n][1] * inv0);
        float2 w1 = make_float2(O[n][2] * inv1, O[n][3] * inv1);
        *(float2*)(o0 + d) = w0;
        *(float2*)(o1 + d) = w1;
    }
}

// ---------------------------------------------------------------------------
extern "C" void kernel_launch(void* const* d_in, const int* in_sizes, int n_in,
                              void* d_out, int out_size)
{
    const float* x    = (const float*)d_in[0];
    const float* rot  = (const float*)d_in[1];
    const float* W    = (const float*)d_in[2];
    const float* bias = (const float*)d_in[3];
    const float* qw   = (const float*)d_in[4];
    const float* kw   = (const float*)d_in[5];
    float* out = (float*)d_out;

    convert_x_kernel<<<(MROWS * DIM) / (256 * 4), 256>>>(x);
    convert_w_kernel<<<dim3(QKV_COLS / 32, DIM / 32), dim3(32, 8)>>>(W);

    cudaFuncSetAttribute(qkv_gemm_mma_kernel,
                         cudaFuncAttributeMaxDynamicSharedMemorySize, GEMM_SMEM);
    qkv_gemm_mma_kernel<<<dim3(QKV_COLS / 256, MROWS / 128), 256, GEMM_SMEM>>>(bias);

    norm_rope_kernel<<<BATCH * NHEADS * SEQ, 128>>>(rot, qw, kw);

    cudaFuncSetAttribute(attn_mma_kernel,
                         cudaFuncAttributeMaxDynamicSharedMemorySize, ATT_SMEM);
    attn_mma_kernel<<<dim3(SEQ / 128, BATCH * NHEADS), 256, ATT_SMEM>>>(out);
}